// round 1
// baseline (speedup 1.0000x reference)
#include <cuda_runtime.h>
#include <cstdint>

// Problem constants (fixed shapes from reference)
#define DIMD     128
#define WINL     32
#define STRIDE   16
#define S_LEN    8192
#define NB       511          // live windows per (b,h); output block 0 is zeros
#define BH       32           // B*H = 2*16
#define WPC      8            // windows per CTA
#define NTHREADS 256
#define KC       16           // K-chunk
#define BSTR     130          // padded Bs row stride (floats)

typedef unsigned long long u64;

__device__ __forceinline__ u64 pack2(float v) {
    u64 r; asm("mov.b64 %0, {%1,%2};" : "=l"(r) : "f"(v), "f"(v)); return r;
}
__device__ __forceinline__ void fma2(u64& d, u64 a, u64 b) {
    asm("fma.rn.f32x2 %0, %1, %2, %0;" : "+l"(d) : "l"(a), "l"(b));
}
__device__ __forceinline__ float2 unpack2(u64 v) {
    float2 f; asm("mov.b64 {%0,%1}, %2;" : "=f"(f.x), "=f"(f.y) : "l"(v)); return f;
}

// One GEMM stage: out[r, n] = act( sum_kc A(r,kc) * W[n, kc] ), N = 128.
// MODE 0: A(r,kc) = ksm[16*(r/16) + 2*(r%16) + (kc>=128)][kc%128] + pe[...]  (K=256)
// MODE 1: A(r,kc) = src[2r + (kc>=128)][kc%128]                              (K=256)
// MODE 2: A(r,kc) = src[r][kc]                                               (K=128)
template<int MODE, int KDIM>
__device__ __forceinline__ void gemm_stage(
    const float* __restrict__ W,   // global weight [128][KDIM]
    const float* src,              // smem source (ksm for MODE 0)
    const float* pes,              // smem pe (MODE 0 only)
    float* Bs, float* dst,
    int Ms, bool do_silu,
    int rowblk, int tx, int tid)
{
    u64 acc[8][4];
#pragma unroll
    for (int i = 0; i < 8; i++)
#pragma unroll
        for (int j = 0; j < 4; j++) acc[i][j] = 0ull;

    const int r0 = rowblk * 8;
    const bool rowActive = (r0 < Ms);

    for (int kb = 0; kb < KDIM; kb += KC) {
        __syncthreads();
        // cooperative load of Bs[kk][n] = W[n][kb+kk]; 2048 elems, 8 per thread
#pragma unroll
        for (int t = 0; t < (KC * 128) / NTHREADS; ++t) {
            int idx = tid + t * NTHREADS;
            int n  = idx >> 4;     // KC == 16
            int kk = idx & 15;
            Bs[kk * BSTR + n] = W[n * KDIM + kb + kk];
        }
        __syncthreads();

        if (rowActive) {
#pragma unroll
            for (int kk = 0; kk < KC; ++kk) {
                const int kc = kb + kk;
                u64 bq[4];
#pragma unroll
                for (int j = 0; j < 4; j++)
                    bq[j] = *(const u64*)(Bs + kk * BSTR + 2 * tx + 32 * j);
#pragma unroll
                for (int i = 0; i < 8; i++) {
                    int r = r0 + i;
                    if (r >= Ms) break;
                    float a;
                    if (MODE == 0) {
                        int l = ((r & 15) << 1) | (kc >> 7);
                        int d = kc & 127;
                        a = src[(((r >> 4) << 4) + l) * DIMD + d] + pes[l * DIMD + d];
                    } else if (MODE == 1) {
                        a = src[(2 * r + (kc >> 7)) * DIMD + (kc & 127)];
                    } else {
                        a = src[r * DIMD + kc];
                    }
                    u64 aa = pack2(a);
#pragma unroll
                    for (int j = 0; j < 4; j++) fma2(acc[i][j], aa, bq[j]);
                }
            }
        }
    }
    __syncthreads();
    // write out (silu fused)
    if (rowActive) {
#pragma unroll
        for (int i = 0; i < 8; i++) {
            int r = r0 + i;
            if (r >= Ms) break;
#pragma unroll
            for (int j = 0; j < 4; j++) {
                float2 v = unpack2(acc[i][j]);
                if (do_silu) {
                    v.x = v.x / (1.f + __expf(-v.x));
                    v.y = v.y / (1.f + __expf(-v.y));
                }
                *(float2*)(dst + r * DIMD + 2 * tx + 32 * j) = v;
            }
        }
    }
}

// SMEM layout (floats):
//   ksm  : 144*128 = 18432
//   pes  : 32*128  =  4096
//   act0 : 128*128 = 16384
//   act1 : 64*128  =  8192
//   Bs   : 16*130  =  2080
// total 49184 floats = 196736 bytes
#define SMEM_FLOATS 49184
#define SMEM_BYTES  (SMEM_FLOATS * 4)

__global__ void __launch_bounds__(NTHREADS, 1)
compressor_kernel(const float* __restrict__ k,
                  const float* __restrict__ pe,
                  const float* __restrict__ w_down,
                  const float* __restrict__ w_stop,
                  float* __restrict__ out)
{
    extern __shared__ float sm[];
    float* ksm  = sm;
    float* pes  = ksm + 144 * 128;
    float* act0 = pes + 4096;
    float* act1 = act0 + 16384;
    float* Bs   = act1 + 8192;

    const int bh    = blockIdx.y;
    const int g     = blockIdx.x;
    const int wbase = g * WPC;
    const int nw    = min(WPC, NB - wbase);
    const int tid   = threadIdx.x;
    const int rowblk = tid >> 4;
    const int tx     = tid & 15;

    // zero block (output window index 0) — out is poisoned, must be written
    if (g == 0 && tid < 128)
        out[(size_t)bh * 512 * DIMD + tid] = 0.f;

    // load pe (32x128)
    {
        const float4* pe4 = (const float4*)pe;
        float4* d4 = (float4*)pes;
        for (int i = tid; i < 4096 / 4; i += NTHREADS) d4[i] = pe4[i];
    }
    // load k region: rows_needed = 16*(nw-1)+32, zero-pad rest of 144 rows
    {
        const int rows = 16 * (nw - 1) + 32;
        const float* kb = k + ((size_t)bh * S_LEN + (size_t)STRIDE * wbase) * DIMD;
        const float4* kb4 = (const float4*)kb;
        float4* d4 = (float4*)ksm;
        const int lim4 = (rows * 128) / 4;
        for (int i = tid; i < (144 * 128) / 4; i += NTHREADS)
            d4[i] = (i < lim4) ? kb4[i] : make_float4(0.f, 0.f, 0.f, 0.f);
    }
    // first gemm_stage's chunk-top double-sync orders these writes before reads

    const int M0 = 16 * nw;
    gemm_stage<0, 256>(w_down + 0 * 128 * 256, ksm,  pes,    Bs, act0, M0,     true,  rowblk, tx, tid);
    gemm_stage<1, 256>(w_down + 1 * 128 * 256, act0, nullptr, Bs, act1, 8 * nw, true,  rowblk, tx, tid);
    gemm_stage<1, 256>(w_down + 2 * 128 * 256, act1, nullptr, Bs, act0, 4 * nw, true,  rowblk, tx, tid);
    gemm_stage<1, 256>(w_down + 3 * 128 * 256, act0, nullptr, Bs, act1, 2 * nw, true,  rowblk, tx, tid);
    gemm_stage<1, 256>(w_down + 4 * 128 * 256, act1, nullptr, Bs, act0, nw,     true,  rowblk, tx, tid);
    gemm_stage<2, 128>(w_stop,                 act0, nullptr, Bs, act1, nw,     false, rowblk, tx, tid);
    __syncthreads();

    // write results: window w -> out[bh, 1 + wbase + w, :]
    for (int idx = tid; idx < nw * 128; idx += NTHREADS) {
        int r = idx >> 7, c = idx & 127;
        out[((size_t)bh * 512 + 1 + wbase + r) * DIMD + c] = act1[idx];
    }
}

extern "C" void kernel_launch(void* const* d_in, const int* in_sizes, int n_in,
                              void* d_out, int out_size)
{
    const float* k  = (const float*)d_in[0];
    const float* pe = (const float*)d_in[1];
    const float* wd = (const float*)d_in[2];
    const float* ws = (const float*)d_in[3];
    float* out = (float*)d_out;

    cudaFuncSetAttribute(compressor_kernel,
                         cudaFuncAttributeMaxDynamicSharedMemorySize, SMEM_BYTES);

    dim3 grid((NB + WPC - 1) / WPC, BH);  // 64 x 32
    compressor_kernel<<<grid, NTHREADS, SMEM_BYTES>>>(k, pe, wd, ws, out);
}

// round 2
// speedup vs baseline: 4.6895x; 4.6895x over previous
#include <cuda_runtime.h>
#include <cuda_bf16.h>
#include <cstdint>

#define DIMD     128
#define STRIDE   16
#define S_LEN    8192
#define NB       511
#define BH       32
#define WPC      8
#define NTHREADS 256
#define WTOT     (5*128*256 + 128*128)   // 180224 weight elements

// pre-split weights (bf16 hi/lo) in device global scratch
__device__ __nv_bfloat16 g_w_hi[WTOT];
__device__ __nv_bfloat16 g_w_lo[WTOT];

__global__ void split_weights_kernel(const float* __restrict__ wd,
                                     const float* __restrict__ ws) {
    int i = blockIdx.x * blockDim.x + threadIdx.x;
    if (i >= WTOT) return;
    float v = (i < 5*128*256) ? wd[i] : ws[i - 5*128*256];
    __nv_bfloat16 h = __float2bfloat16(v);
    g_w_hi[i] = h;
    g_w_lo[i] = __float2bfloat16(v - __bfloat162float(h));
}

__device__ __forceinline__ uint32_t u32p(const void* p) {
    return (uint32_t)__cvta_generic_to_shared(p);
}
__device__ __forceinline__ void ldmx4(uint32_t* r, uint32_t addr) {
    asm volatile("ldmatrix.sync.aligned.m8n8.x4.shared.b16 {%0,%1,%2,%3}, [%4];"
                 : "=r"(r[0]), "=r"(r[1]), "=r"(r[2]), "=r"(r[3]) : "r"(addr));
}
__device__ __forceinline__ void mma16816(float* c, const uint32_t* a,
                                         uint32_t b0, uint32_t b1) {
    asm volatile("mma.sync.aligned.m16n8k16.row.col.f32.bf16.bf16.f32 "
                 "{%0,%1,%2,%3}, {%4,%5,%6,%7}, {%8,%9}, {%0,%1,%2,%3};"
                 : "+f"(c[0]), "+f"(c[1]), "+f"(c[2]), "+f"(c[3])
                 : "r"(a[0]), "r"(a[1]), "r"(a[2]), "r"(a[3]), "r"(b0), "r"(b1));
}
__device__ __forceinline__ float silu_f(float x) {
    return x / (1.f + __expf(-x));
}

union U8b { __nv_bfloat16 b[8]; uint4 v; };
union U2b { __nv_bfloat16 b[2]; uint32_t u; };

// ---------------------------------------------------------------------------
// One GEMM stage on tensor cores.
// AMODE 0: A from per-chunk staged A0 buffer [128 rows x 64 k] (stage 0)
// AMODE 1: A from act buffer [2*Ms rows x 128] read as pairs (K=256)
// AMODE 2: A from act buffer [Ms rows x 128] direct (K=128)
// OUTMODE 0: silu + split-bf16 store to act out buffers
// OUTMODE 1: fp32 store to gmem (no silu)
// ---------------------------------------------------------------------------
template<int AMODE, int OUTMODE>
__device__ __forceinline__ void run_stage(
    int Ms, int KDIM, int nw,
    const __nv_bfloat16* __restrict__ wh, const __nv_bfloat16* __restrict__ wl,
    uint32_t aHiU, uint32_t aLoU,
    uint32_t bHiU, uint32_t bLoU,
    __nv_bfloat16* sBhi, __nv_bfloat16* sBlo,
    __nv_bfloat16* sA0hi, __nv_bfloat16* sA0lo,
    char* outHi, char* outLo,
    float* gout,
    const float* kbase, const float* pes)
{
    const int tid  = threadIdx.x;
    const int lane = tid & 31;
    const int wid  = tid >> 5;

    // padded row-tile count: power of two in {1,2,4,8}
    int RTp = 1;
    while (RTp * 16 < Ms) RTp <<= 1;
    const int NTW   = 2 * RTp;          // n-tiles per warp
    const int rt    = wid & (RTp - 1);  // this warp's row tile
    const int ntBeg = (wid / RTp) * NTW;

    float acc[16][4];
#pragma unroll
    for (int i = 0; i < 16; i++)
#pragma unroll
        for (int j = 0; j < 4; j++) acc[i][j] = 0.f;

    // per-lane ldmatrix constants
    const int a_mat    = lane >> 3;
    const int a_rowoff = (lane & 7) + ((a_mat & 1) << 3);
    const int a_koff   = (a_mat >> 1) << 3;
    const int b_nl     = lane & 7;
    const int b_km     = (lane >> 3) << 3;

    for (int kb = 0; kb < KDIM; kb += 64) {
        __syncthreads();
        // ---- stage B chunk [128 n x 64 k] hi+lo, swizzle chunk^(n&7) ----
#pragma unroll
        for (int it = 0; it < 2048 / NTHREADS; ++it) {
            int i = tid + it * NTHREADS;
            int hl = i & 1, chunk = (i >> 1) & 7, n = i >> 4;
            const __nv_bfloat16* src = (hl ? wl : wh) + n * KDIM + kb + chunk * 8;
            uint4 v = *(const uint4*)src;
            __nv_bfloat16* dst = (hl ? sBlo : sBhi) + n * 64 + ((chunk ^ (n & 7)) << 3);
            *(uint4*)dst = v;
        }
        // ---- stage A0 chunk (stage 0 only): (k + pe) split to bf16 ----
        if (AMODE == 0) {
            const int bsel = kb >> 7, d0 = kb & 127;
#pragma unroll
            for (int it = 0; it < 1024 / NTHREADS; ++it) {
                int i = tid + it * NTHREADS;
                int R = i >> 3, chunk = i & 7;
                int d = d0 + (chunk << 3);
                int l = 2 * (R & 15) + bsel;
                float v[8];
                if (R < 16 * nw) {
                    int srow = ((R >> 4) << 4) + l;
                    const float* kp = kbase + (size_t)srow * DIMD + d;
                    const float* pp = pes + l * DIMD + d;
                    float4 f0 = *(const float4*)kp, f1 = *(const float4*)(kp + 4);
                    float4 p0 = *(const float4*)pp, p1 = *(const float4*)(pp + 4);
                    v[0] = f0.x + p0.x; v[1] = f0.y + p0.y;
                    v[2] = f0.z + p0.z; v[3] = f0.w + p0.w;
                    v[4] = f1.x + p1.x; v[5] = f1.y + p1.y;
                    v[6] = f1.z + p1.z; v[7] = f1.w + p1.w;
                } else {
#pragma unroll
                    for (int j = 0; j < 8; j++) v[j] = 0.f;
                }
                U8b hi, lo;
#pragma unroll
                for (int j = 0; j < 8; j++) {
                    hi.b[j] = __float2bfloat16(v[j]);
                    lo.b[j] = __float2bfloat16(v[j] - __bfloat162float(hi.b[j]));
                }
                int co = (chunk ^ (R & 7)) << 3;
                *(uint4*)(sA0hi + R * 64 + co) = hi.v;
                *(uint4*)(sA0lo + R * 64 + co) = lo.v;
            }
        }
        __syncthreads();

        // ---- compute: this warp's row tile x its n-tiles ----
#pragma unroll
        for (int kq = 0; kq < 64; kq += 32) {
            // A fragment byte offsets for ksteps kq and kq+16
            int offs0, offs1;
            {
                int R = (rt << 4) + a_rowoff;
                if (AMODE == 0) {
                    int kc0 = kq + a_koff;
                    offs0 = R * 128 + (((kc0 >> 3) ^ (R & 7)) << 4);
                    int kc1 = kc0 + 16;
                    offs1 = R * 128 + (((kc1 >> 3) ^ (R & 7)) << 4);
                } else if (AMODE == 1) {
                    int k0 = kb + kq + a_koff;
                    int pr0 = 2 * R + (k0 >> 7);
                    int c0 = k0 & 127, ch0 = c0 >> 3;
                    int cs0 = (ch0 & 8) | ((ch0 & 7) ^ ((pr0 >> 1) & 7));
                    offs0 = pr0 * 256 + (cs0 << 4);
                    int k1 = k0 + 16;
                    int pr1 = 2 * R + (k1 >> 7);
                    int c1 = k1 & 127, ch1 = c1 >> 3;
                    int cs1 = (ch1 & 8) | ((ch1 & 7) ^ ((pr1 >> 1) & 7));
                    offs1 = pr1 * 256 + (cs1 << 4);
                } else {
                    int k0 = kb + kq + a_koff;
                    int ch0 = k0 >> 3;
                    int cs0 = (ch0 & 8) | ((ch0 & 7) ^ ((R >> 1) & 7));
                    offs0 = R * 256 + (cs0 << 4);
                    int k1 = k0 + 16;
                    int ch1 = k1 >> 3;
                    int cs1 = (ch1 & 8) | ((ch1 & 7) ^ ((R >> 1) & 7));
                    offs1 = R * 256 + (cs1 << 4);
                }
            }
            uint32_t aH[8], aL[8];
            ldmx4(aH + 0, aHiU + offs0);
            ldmx4(aH + 4, aHiU + offs1);
            ldmx4(aL + 0, aLoU + offs0);
            ldmx4(aL + 4, aLoU + offs1);

#pragma unroll
            for (int ai = 0; ai < 16; ai++) {
                if (ai >= NTW) break;
                int nt = ntBeg + ai;
                int n  = (nt << 3) + b_nl;
                int kcm = kq + b_km;
                int cs = (kcm >> 3) ^ (n & 7);
                uint32_t boff = n * 128 + (cs << 4);
                uint32_t bH[4], bL[4];
                ldmx4(bH, bHiU + boff);
                ldmx4(bL, bLoU + boff);
                float* c = acc[ai];
                mma16816(c, aH + 0, bH[0], bH[1]);
                mma16816(c, aL + 0, bH[0], bH[1]);
                mma16816(c, aH + 0, bL[0], bL[1]);
                mma16816(c, aH + 4, bH[2], bH[3]);
                mma16816(c, aL + 4, bH[2], bH[3]);
                mma16816(c, aH + 4, bL[2], bL[3]);
            }
        }
    }

    // ---- epilogue ----
    const int r0  = (rt << 4) + (lane >> 2);
    const int cof = (lane & 3) << 1;
#pragma unroll
    for (int ai = 0; ai < 16; ai++) {
        if (ai >= NTW) break;
        int nt = ntBeg + ai;
        int col = (nt << 3) + cof;
        float* c = acc[ai];
#pragma unroll
        for (int h = 0; h < 2; h++) {
            int r = r0 + (h << 3);
            if (r < Ms) {
                float v0 = c[2 * h], v1 = c[2 * h + 1];
                if (OUTMODE == 0) {
                    v0 = silu_f(v0); v1 = silu_f(v1);
                    U2b hi, lo;
                    hi.b[0] = __float2bfloat16(v0);
                    hi.b[1] = __float2bfloat16(v1);
                    lo.b[0] = __float2bfloat16(v0 - __bfloat162float(hi.b[0]));
                    lo.b[1] = __float2bfloat16(v1 - __bfloat162float(hi.b[1]));
                    int cs = (nt & 8) | ((nt & 7) ^ ((r >> 1) & 7));
                    int off = r * 256 + (cs << 4) + ((col & 7) << 1);
                    *(uint32_t*)(outHi + off) = hi.u;
                    *(uint32_t*)(outLo + off) = lo.u;
                } else {
                    gout[(size_t)r * DIMD + col]     = v0;
                    gout[(size_t)r * DIMD + col + 1] = v1;
                }
            }
        }
    }
}

// SMEM layout (bytes from dynamic base):
//   0      : pe fp32            16384
//   16384  : actP_hi (128x256B) 32768
//   49152  : actP_lo            32768
//   81920  : actQ_hi (64x256B)  16384
//   98304  : actQ_lo            16384
//   114688 : A0_hi  (128x128B)  16384
//   131072 : A0_lo              16384
//   147456 : B_hi   (128x128B)  16384
//   163840 : B_lo               16384
#define SMEM_BYTES 180224

__global__ void __launch_bounds__(NTHREADS, 1)
compressor_mma_kernel(const float* __restrict__ k,
                      const float* __restrict__ pe,
                      float* __restrict__ out)
{
    extern __shared__ char sm[];
    float* pes  = (float*)sm;
    char* actPhi = sm + 16384;
    char* actPlo = sm + 49152;
    char* actQhi = sm + 81920;
    char* actQlo = sm + 98304;
    __nv_bfloat16* a0hi = (__nv_bfloat16*)(sm + 114688);
    __nv_bfloat16* a0lo = (__nv_bfloat16*)(sm + 131072);
    __nv_bfloat16* bhi  = (__nv_bfloat16*)(sm + 147456);
    __nv_bfloat16* blo  = (__nv_bfloat16*)(sm + 163840);

    const uint32_t uPhi = u32p(actPhi), uPlo = u32p(actPlo);
    const uint32_t uQhi = u32p(actQhi), uQlo = u32p(actQlo);
    const uint32_t uAhi = u32p(a0hi),   uAlo = u32p(a0lo);
    const uint32_t uBhi = u32p(bhi),    uBlo = u32p(blo);

    const int bh    = blockIdx.y;
    const int g     = blockIdx.x;
    const int wbase = g * WPC;
    const int nw    = min(WPC, NB - wbase);
    const int tid   = threadIdx.x;

    // zero block: out[bh][0][:]
    if (g == 0 && tid < DIMD)
        out[(size_t)bh * 512 * DIMD + tid] = 0.f;

    // load pe (32x128 fp32)
    {
        const float4* s4 = (const float4*)pe;
        float4* d4 = (float4*)pes;
        for (int i = tid; i < 4096 / 4; i += NTHREADS) d4[i] = s4[i];
    }
    // (ordered before first use by the stage's top-of-chunk __syncthreads)

    const float* kbase = k + ((size_t)bh * S_LEN + (size_t)STRIDE * wbase) * DIMD;
    float* gout = out + ((size_t)bh * 512 + 1 + wbase) * DIMD;

    const __nv_bfloat16* wh = g_w_hi;
    const __nv_bfloat16* wl = g_w_lo;

    run_stage<0,0>(16*nw, 256, nw, wh,          wl,          uAhi, uAlo, uBhi, uBlo,
                   bhi, blo, a0hi, a0lo, actPhi, actPlo, nullptr, kbase, pes);
    run_stage<1,0>(8*nw,  256, nw, wh+32768,    wl+32768,    uPhi, uPlo, uBhi, uBlo,
                   bhi, blo, a0hi, a0lo, actQhi, actQlo, nullptr, kbase, pes);
    run_stage<1,0>(4*nw,  256, nw, wh+65536,    wl+65536,    uQhi, uQlo, uBhi, uBlo,
                   bhi, blo, a0hi, a0lo, actPhi, actPlo, nullptr, kbase, pes);
    run_stage<1,0>(2*nw,  256, nw, wh+98304,    wl+98304,    uPhi, uPlo, uBhi, uBlo,
                   bhi, blo, a0hi, a0lo, actQhi, actQlo, nullptr, kbase, pes);
    run_stage<1,0>(nw,    256, nw, wh+131072,   wl+131072,   uQhi, uQlo, uBhi, uBlo,
                   bhi, blo, a0hi, a0lo, actPhi, actPlo, nullptr, kbase, pes);
    run_stage<2,1>(nw,    128, nw, wh+163840,   wl+163840,   uPhi, uPlo, uBhi, uBlo,
                   bhi, blo, a0hi, a0lo, nullptr, nullptr, gout,  kbase, pes);
}

extern "C" void kernel_launch(void* const* d_in, const int* in_sizes, int n_in,
                              void* d_out, int out_size)
{
    const float* k  = (const float*)d_in[0];
    const float* pe = (const float*)d_in[1];
    const float* wd = (const float*)d_in[2];
    const float* ws = (const float*)d_in[3];
    float* out = (float*)d_out;

    split_weights_kernel<<<(WTOT + 255) / 256, 256>>>(wd, ws);

    cudaFuncSetAttribute(compressor_mma_kernel,
                         cudaFuncAttributeMaxDynamicSharedMemorySize, SMEM_BYTES);
    dim3 grid((NB + WPC - 1) / WPC, BH);  // 64 x 32
    compressor_mma_kernel<<<grid, NTHREADS, SMEM_BYTES>>>(k, pe, out);
}

// round 3
// speedup vs baseline: 6.0065x; 1.2808x over previous
#include <cuda_runtime.h>
#include <cuda_bf16.h>
#include <cstdint>

#define DIMD     128
#define STRIDE   16
#define S_LEN    8192
#define NB       511
#define BH       32
#define WPC      8
#define NTHREADS 256
#define WTOT     (5*128*256 + 128*128)
#define KTOT     ((size_t)BH * S_LEN * DIMD)   // 33,554,432

// device scratch: split weights, split k, pe-bias
__device__ __nv_bfloat16 g_w_hi[WTOT];
__device__ __nv_bfloat16 g_w_lo[WTOT];
__device__ __nv_bfloat16 g_k_hi[KTOT];
__device__ __nv_bfloat16 g_k_lo[KTOT];
__device__ float         g_pew[16 * 128];

union U8b { __nv_bfloat16 b[8]; uint4 v; };
union U2b { __nv_bfloat16 b[2]; uint32_t u; };

__global__ void split_weights_kernel(const float* __restrict__ wd,
                                     const float* __restrict__ ws) {
    int i = blockIdx.x * blockDim.x + threadIdx.x;
    if (i >= WTOT) return;
    float v = (i < 5*128*256) ? wd[i] : ws[i - 5*128*256];
    __nv_bfloat16 h = __float2bfloat16(v);
    g_w_hi[i] = h;
    g_w_lo[i] = __float2bfloat16(v - __bfloat162float(h));
}

__global__ void split_k_kernel(const float* __restrict__ k) {
    size_t i = ((size_t)blockIdx.x * blockDim.x + threadIdx.x) * 8;
    float4 f0 = *(const float4*)(k + i);
    float4 f1 = *(const float4*)(k + i + 4);
    float v[8] = {f0.x, f0.y, f0.z, f0.w, f1.x, f1.y, f1.z, f1.w};
    U8b hi, lo;
#pragma unroll
    for (int j = 0; j < 8; j++) {
        hi.b[j] = __float2bfloat16(v[j]);
        lo.b[j] = __float2bfloat16(v[j] - __bfloat162float(hi.b[j]));
    }
    *(uint4*)(g_k_hi + i) = hi.v;
    *(uint4*)(g_k_lo + i) = lo.v;
}

// PEW[j][n] = sum_d pe[2j,d]*W0[n,d] + pe[2j+1,d]*W0[n,128+d]
__global__ void prep_pew_kernel(const float* __restrict__ wd,
                                const float* __restrict__ pe) {
    int idx = blockIdx.x * blockDim.x + threadIdx.x;   // 2048 total
    int j = idx >> 7, n = idx & 127;
    float s = 0.f;
    for (int d = 0; d < 128; ++d) {
        s += pe[(2*j)*128 + d]     * wd[n*256 + d];
        s += pe[(2*j+1)*128 + d]   * wd[n*256 + 128 + d];
    }
    g_pew[idx] = s;
}

// ---------------------------------------------------------------------------

__device__ __forceinline__ uint32_t u32p(const void* p) {
    return (uint32_t)__cvta_generic_to_shared(p);
}
__device__ __forceinline__ void ldmx4(uint32_t* r, uint32_t addr) {
    asm volatile("ldmatrix.sync.aligned.m8n8.x4.shared.b16 {%0,%1,%2,%3}, [%4];"
                 : "=r"(r[0]), "=r"(r[1]), "=r"(r[2]), "=r"(r[3]) : "r"(addr));
}
__device__ __forceinline__ void mma16816(float* c, const uint32_t* a,
                                         uint32_t b0, uint32_t b1) {
    asm volatile("mma.sync.aligned.m16n8k16.row.col.f32.bf16.bf16.f32 "
                 "{%0,%1,%2,%3}, {%4,%5,%6,%7}, {%8,%9}, {%0,%1,%2,%3};"
                 : "+f"(c[0]), "+f"(c[1]), "+f"(c[2]), "+f"(c[3])
                 : "r"(a[0]), "r"(a[1]), "r"(a[2]), "r"(a[3]), "r"(b0), "r"(b1));
}
__device__ __forceinline__ float silu_f(float x) { return x / (1.f + __expf(-x)); }

__device__ __forceinline__ void cpasync16(uint32_t dst, const void* src, bool valid) {
    int sz = valid ? 16 : 0;
    asm volatile("cp.async.cg.shared.global [%0], [%1], 16, %2;"
                 :: "r"(dst), "l"(src), "r"(sz));
}
__device__ __forceinline__ void cpcommit() {
    asm volatile("cp.async.commit_group;" ::: "memory");
}
__device__ __forceinline__ void cpwait0() { asm volatile("cp.async.wait_group 0;" ::: "memory"); }
__device__ __forceinline__ void cpwait1() { asm volatile("cp.async.wait_group 1;" ::: "memory"); }

// SMEM layout (byte offsets from dynamic base):
#define OFF_ACTP_HI 0
#define OFF_ACTP_LO 32768
#define OFF_ACTQ_HI 65536
#define OFF_ACTQ_LO 81920
#define OFF_A0(b)   (98304  + (b)*32768)   // hi at +0, lo at +16384
#define OFF_B(b)    (163840 + (b)*32768)
#define SMEM_BYTES  229376

// stage B weights chunk: [128 n x 64 k] hi+lo, swizzled, via cp.async
__device__ __forceinline__ void prefetch_B(uint32_t bufU,
        const __nv_bfloat16* __restrict__ wh, const __nv_bfloat16* __restrict__ wl,
        int kb, int KDIM, int tid) {
#pragma unroll
    for (int it = 0; it < 8; ++it) {
        int i = tid + it * NTHREADS;
        int g = i & 7, n = (i >> 3) & 127, hl = i >> 10;
        const __nv_bfloat16* src = (hl ? wl : wh) + n * KDIM + kb + g * 8;
        uint32_t dst = bufU + hl * 16384 + n * 128 + ((g ^ (n & 7)) << 4);
        cpasync16(dst, src, true);
    }
}

// stage0 A chunk: rows R<128 map to window pairs, from pre-split k
__device__ __forceinline__ void prefetch_A0(uint32_t bufU,
        const __nv_bfloat16* __restrict__ khB, const __nv_bfloat16* __restrict__ klB,
        int kb, int nw, int tid) {
    const int bsel = kb >> 7, d0 = kb & 127;
#pragma unroll
    for (int it = 0; it < 8; ++it) {
        int i = tid + it * NTHREADS;
        int g = i & 7, R = (i >> 3) & 127, hl = i >> 10;
        bool valid = R < 16 * nw;
        int srow = ((R >> 4) << 4) + 2 * (R & 15) + bsel;
        const __nv_bfloat16* base = hl ? klB : khB;
        const __nv_bfloat16* src = base + (size_t)(valid ? srow : 0) * DIMD + d0 + g * 8;
        uint32_t dst = bufU + hl * 16384 + R * 128 + ((g ^ (R & 7)) << 4);
        cpasync16(dst, src, valid);
    }
}

// ---------------------------------------------------------------------------
// One GEMM stage. Warp computes R row-tiles x T n-tiles. NWR = warps per row dim.
// AMODE 0: A from double-buffered A0 (stage 0, pre-split k, swizzled 64-col chunks)
// AMODE 1: A from act buffer paired rows (K=256)
// AMODE 2: A from act buffer direct (K=128)
// OUTMODE 0: silu + split-bf16 store to act out; OUTMODE 1: fp32 store to gmem
// ---------------------------------------------------------------------------
template<int AMODE, int OUTMODE, int R, int T, int NWR>
__device__ __forceinline__ void run_stage(
    int Ms, int KDIM, int nw,
    const __nv_bfloat16* __restrict__ wh, const __nv_bfloat16* __restrict__ wl,
    const __nv_bfloat16* __restrict__ khB, const __nv_bfloat16* __restrict__ klB,
    uint32_t sb,
    uint32_t aHiU, uint32_t aLoU,      // act source (AMODE 1/2)
    char* outHi, char* outLo,          // act dest (OUTMODE 0)
    float* gout)                        // gmem dest (OUTMODE 1)
{
    const int tid  = threadIdx.x;
    const int lane = tid & 31;
    const int wid  = tid >> 5;
    const int rBeg  = (wid % NWR) * R;
    const int ntBeg = (wid / NWR) * T;

    float acc[R][T][4];
#pragma unroll
    for (int i = 0; i < R; i++)
#pragma unroll
        for (int t = 0; t < T; t++)
#pragma unroll
            for (int j = 0; j < 4; j++) acc[i][t][j] = 0.f;

    const int a_mat    = lane >> 3;
    const int a_rowoff = (lane & 7) + ((a_mat & 1) << 3);
    const int a_koff   = (a_mat >> 1) << 3;
    const int b_nl     = lane & 7;
    const int b_km     = (lane >> 3) << 3;

    const int NC = KDIM / 64;

    // prologue prefetch
    prefetch_B(sb + OFF_B(0), wh, wl, 0, KDIM, tid);
    if (AMODE == 0) prefetch_A0(sb + OFF_A0(0), khB, klB, 0, nw, tid);
    cpcommit();

    for (int c = 0; c < NC; ++c) {
        if (c + 1 < NC) {
            int b = (c + 1) & 1;
            prefetch_B(sb + OFF_B(b), wh, wl, (c + 1) * 64, KDIM, tid);
            if (AMODE == 0) prefetch_A0(sb + OFF_A0(b), khB, klB, (c + 1) * 64, nw, tid);
            cpcommit();
            cpwait1();
        } else {
            cpwait0();
        }
        __syncthreads();

        const int kb = c * 64;
        const int bi = c & 1;
        const uint32_t bHiU = sb + OFF_B(bi);
        const uint32_t bLoU = bHiU + 16384;
        uint32_t srcHi, srcLo;
        if (AMODE == 0) { srcHi = sb + OFF_A0(bi); srcLo = srcHi + 16384; }
        else            { srcHi = aHiU;            srcLo = aLoU; }

#pragma unroll
        for (int kq = 0; kq < 64; kq += 32) {
            uint32_t aH[R][8], aL[R][8];
#pragma unroll
            for (int i = 0; i < R; i++) {
                const int Rr = (rBeg + i) * 16 + a_rowoff;
                int offs0, offs1;
                if (AMODE == 0) {
                    int kc0 = kq + a_koff;
                    offs0 = Rr * 128 + (((kc0 >> 3) ^ (Rr & 7)) << 4);
                    int kc1 = kc0 + 16;
                    offs1 = Rr * 128 + (((kc1 >> 3) ^ (Rr & 7)) << 4);
                } else if (AMODE == 1) {
                    int k0 = kb + kq + a_koff;
                    int pr0 = 2 * Rr + (k0 >> 7);
                    int ch0 = (k0 & 127) >> 3;
                    int cs0 = (ch0 & 8) | ((ch0 & 7) ^ ((pr0 >> 1) & 7));
                    offs0 = pr0 * 256 + (cs0 << 4);
                    int k1 = k0 + 16;
                    int pr1 = 2 * Rr + (k1 >> 7);
                    int ch1 = (k1 & 127) >> 3;
                    int cs1 = (ch1 & 8) | ((ch1 & 7) ^ ((pr1 >> 1) & 7));
                    offs1 = pr1 * 256 + (cs1 << 4);
                } else {
                    int k0 = kb + kq + a_koff;
                    int ch0 = k0 >> 3;
                    int cs0 = (ch0 & 8) | ((ch0 & 7) ^ ((Rr >> 1) & 7));
                    offs0 = Rr * 256 + (cs0 << 4);
                    int k1 = k0 + 16;
                    int ch1 = k1 >> 3;
                    int cs1 = (ch1 & 8) | ((ch1 & 7) ^ ((Rr >> 1) & 7));
                    offs1 = Rr * 256 + (cs1 << 4);
                }
                ldmx4(aH[i] + 0, srcHi + offs0);
                ldmx4(aH[i] + 4, srcHi + offs1);
                ldmx4(aL[i] + 0, srcLo + offs0);
                ldmx4(aL[i] + 4, srcLo + offs1);
            }
#pragma unroll
            for (int t = 0; t < T; t++) {
                const int nt = ntBeg + t;
                const int n = (nt << 3) + b_nl;
                const int cs = ((kq + b_km) >> 3) ^ (n & 7);
                const uint32_t boff = n * 128 + (cs << 4);
                uint32_t bH[4], bL[4];
                ldmx4(bH, bHiU + boff);
                ldmx4(bL, bLoU + boff);
#pragma unroll
                for (int i = 0; i < R; i++) {
                    float* cc = acc[i][t];
                    mma16816(cc, aH[i] + 0, bH[0], bH[1]);
                    mma16816(cc, aL[i] + 0, bH[0], bH[1]);
                    mma16816(cc, aH[i] + 0, bL[0], bL[1]);
                    mma16816(cc, aH[i] + 4, bH[2], bH[3]);
                    mma16816(cc, aL[i] + 4, bH[2], bH[3]);
                    mma16816(cc, aH[i] + 4, bL[2], bL[3]);
                }
            }
        }
    }
    __syncthreads();   // protect B/A0 buffers + order before next stage

    // epilogue
    const int r0  = lane >> 2;
    const int cof = (lane & 3) << 1;
#pragma unroll
    for (int i = 0; i < R; i++) {
#pragma unroll
        for (int t = 0; t < T; t++) {
            const int nt = ntBeg + t;
            const int col = (nt << 3) + cof;
            float* cc = acc[i][t];
#pragma unroll
            for (int h = 0; h < 2; h++) {
                const int r = (rBeg + i) * 16 + r0 + (h << 3);
                if (r < Ms) {
                    float v0 = cc[2*h], v1 = cc[2*h + 1];
                    if (AMODE == 0) {   // stage-0 pe bias, fp32
                        float2 bb = *(const float2*)(g_pew + (r & 15) * 128 + col);
                        v0 += bb.x; v1 += bb.y;
                    }
                    if (OUTMODE == 0) {
                        v0 = silu_f(v0); v1 = silu_f(v1);
                        U2b hi, lo;
                        hi.b[0] = __float2bfloat16(v0);
                        hi.b[1] = __float2bfloat16(v1);
                        lo.b[0] = __float2bfloat16(v0 - __bfloat162float(hi.b[0]));
                        lo.b[1] = __float2bfloat16(v1 - __bfloat162float(hi.b[1]));
                        int cs = (nt & 8) | ((nt & 7) ^ ((r >> 1) & 7));
                        int off = r * 256 + (cs << 4) + ((col & 7) << 1);
                        *(uint32_t*)(outHi + off) = hi.u;
                        *(uint32_t*)(outLo + off) = lo.u;
                    } else {
                        gout[(size_t)r * DIMD + col]     = v0;
                        gout[(size_t)r * DIMD + col + 1] = v1;
                    }
                }
            }
        }
    }
}

__global__ void __launch_bounds__(NTHREADS, 1)
compressor_mma_kernel(float* __restrict__ out)
{
    extern __shared__ char sm[];
    const uint32_t sb = u32p(sm);
    char* actPhi = sm + OFF_ACTP_HI;
    char* actPlo = sm + OFF_ACTP_LO;
    char* actQhi = sm + OFF_ACTQ_HI;
    char* actQlo = sm + OFF_ACTQ_LO;
    const uint32_t uPhi = sb + OFF_ACTP_HI, uPlo = sb + OFF_ACTP_LO;
    const uint32_t uQhi = sb + OFF_ACTQ_HI, uQlo = sb + OFF_ACTQ_LO;

    const int bh    = blockIdx.y;
    const int g     = blockIdx.x;
    const int wbase = g * WPC;
    const int nw    = min(WPC, NB - wbase);
    const int tid   = threadIdx.x;

    if (g == 0 && tid < DIMD)
        out[(size_t)bh * 512 * DIMD + tid] = 0.f;

    const __nv_bfloat16* khB = g_k_hi + ((size_t)bh * S_LEN + (size_t)STRIDE * wbase) * DIMD;
    const __nv_bfloat16* klB = g_k_lo + ((size_t)bh * S_LEN + (size_t)STRIDE * wbase) * DIMD;
    float* gout = out + ((size_t)bh * 512 + 1 + wbase) * DIMD;

    const __nv_bfloat16* wh = g_w_hi;
    const __nv_bfloat16* wl = g_w_lo;

    run_stage<0,0,2,8,4>(16*nw, 256, nw, wh,        wl,        khB, klB, sb, 0, 0,
                         actPhi, actPlo, nullptr);
    run_stage<1,0,2,4,2>(8*nw,  256, nw, wh+32768,  wl+32768,  nullptr, nullptr, sb,
                         uPhi, uPlo, actQhi, actQlo, nullptr);
    run_stage<1,0,2,2,1>(4*nw,  256, nw, wh+65536,  wl+65536,  nullptr, nullptr, sb,
                         uQhi, uQlo, actPhi, actPlo, nullptr);
    run_stage<1,0,1,2,1>(2*nw,  256, nw, wh+98304,  wl+98304,  nullptr, nullptr, sb,
                         uPhi, uPlo, actQhi, actQlo, nullptr);
    run_stage<1,0,1,2,1>(nw,    256, nw, wh+131072, wl+131072, nullptr, nullptr, sb,
                         uQhi, uQlo, actPhi, actPlo, nullptr);
    run_stage<2,1,1,2,1>(nw,    128, nw, wh+163840, wl+163840, nullptr, nullptr, sb,
                         uPhi, uPlo, nullptr, nullptr, gout);
}

extern "C" void kernel_launch(void* const* d_in, const int* in_sizes, int n_in,
                              void* d_out, int out_size)
{
    const float* k  = (const float*)d_in[0];
    const float* pe = (const float*)d_in[1];
    const float* wd = (const float*)d_in[2];
    const float* ws = (const float*)d_in[3];
    float* out = (float*)d_out;

    split_weights_kernel<<<(WTOT + 255) / 256, 256>>>(wd, ws);
    split_k_kernel<<<(int)(KTOT / (256 * 8)), 256>>>(k);
    prep_pew_kernel<<<8, 256>>>(wd, pe);

    cudaFuncSetAttribute(compressor_mma_kernel,
                         cudaFuncAttributeMaxDynamicSharedMemorySize, SMEM_BYTES);
    dim3 grid((NB + WPC - 1) / WPC, BH);  // 64 x 32
    compressor_mma_kernel<<<grid, NTHREADS, SMEM_BYTES>>>(out);
}

// round 5
// speedup vs baseline: 6.4641x; 1.0762x over previous
#include <cuda_runtime.h>
#include <cuda_bf16.h>
#include <cstdint>

#define DIMD     128
#define STRIDE   16
#define S_LEN    8192
#define NB       511
#define BH       32
#define WPC      8
#define NTHREADS 512
#define WTOT     (5*128*256 + 128*128)
#define KTOT     ((size_t)BH * S_LEN * DIMD)   // 33,554,432

// device scratch: split weights, split k, pe-bias
__device__ __nv_bfloat16 g_w_hi[WTOT];
__device__ __nv_bfloat16 g_w_lo[WTOT];
__device__ __nv_bfloat16 g_k_hi[KTOT];
__device__ __nv_bfloat16 g_k_lo[KTOT];
__device__ float         g_pew[16 * 128];

union U8b { __nv_bfloat16 b[8]; uint4 v; };
union U2b { __nv_bfloat16 b[2]; uint32_t u; };

__global__ void split_weights_kernel(const float* __restrict__ wd,
                                     const float* __restrict__ ws) {
    int i = blockIdx.x * blockDim.x + threadIdx.x;
    if (i >= WTOT) return;
    float v = (i < 5*128*256) ? wd[i] : ws[i - 5*128*256];
    __nv_bfloat16 h = __float2bfloat16(v);
    g_w_hi[i] = h;
    g_w_lo[i] = __float2bfloat16(v - __bfloat162float(h));
}

__global__ void split_k_kernel(const float* __restrict__ k) {
    size_t i = ((size_t)blockIdx.x * blockDim.x + threadIdx.x) * 8;
    float4 f0 = *(const float4*)(k + i);
    float4 f1 = *(const float4*)(k + i + 4);
    float v[8] = {f0.x, f0.y, f0.z, f0.w, f1.x, f1.y, f1.z, f1.w};
    U8b hi, lo;
#pragma unroll
    for (int j = 0; j < 8; j++) {
        hi.b[j] = __float2bfloat16(v[j]);
        lo.b[j] = __float2bfloat16(v[j] - __bfloat162float(hi.b[j]));
    }
    *(uint4*)(g_k_hi + i) = hi.v;
    *(uint4*)(g_k_lo + i) = lo.v;
}

// PEW[j][n] = sum_d pe[2j,d]*W0[n,d] + pe[2j+1,d]*W0[n,128+d]
__global__ void prep_pew_kernel(const float* __restrict__ wd,
                                const float* __restrict__ pe) {
    int idx = blockIdx.x * blockDim.x + threadIdx.x;   // 2048 total
    int j = idx >> 7, n = idx & 127;
    float s = 0.f;
    for (int d = 0; d < 128; ++d) {
        s += pe[(2*j)*128 + d]   * wd[n*256 + d];
        s += pe[(2*j+1)*128 + d] * wd[n*256 + 128 + d];
    }
    g_pew[idx] = s;
}

// ---------------------------------------------------------------------------

__device__ __forceinline__ uint32_t u32p(const void* p) {
    return (uint32_t)__cvta_generic_to_shared(p);
}
__device__ __forceinline__ void ldmx4(uint32_t* r, uint32_t addr) {
    asm volatile("ldmatrix.sync.aligned.m8n8.x4.shared.b16 {%0,%1,%2,%3}, [%4];"
                 : "=r"(r[0]), "=r"(r[1]), "=r"(r[2]), "=r"(r[3]) : "r"(addr));
}
__device__ __forceinline__ void mma16816(float* c, const uint32_t* a,
                                         uint32_t b0, uint32_t b1) {
    asm volatile("mma.sync.aligned.m16n8k16.row.col.f32.bf16.bf16.f32 "
                 "{%0,%1,%2,%3}, {%4,%5,%6,%7}, {%8,%9}, {%0,%1,%2,%3};"
                 : "+f"(c[0]), "+f"(c[1]), "+f"(c[2]), "+f"(c[3])
                 : "r"(a[0]), "r"(a[1]), "r"(a[2]), "r"(a[3]), "r"(b0), "r"(b1));
}
__device__ __forceinline__ float silu_f(float x) { return x / (1.f + __expf(-x)); }

__device__ __forceinline__ void cpasync16(uint32_t dst, const void* src, bool valid) {
    int sz = valid ? 16 : 0;
    asm volatile("cp.async.cg.shared.global [%0], [%1], 16, %2;"
                 :: "r"(dst), "l"(src), "r"(sz));
}
__device__ __forceinline__ void cpcommit() {
    asm volatile("cp.async.commit_group;" ::: "memory");
}
__device__ __forceinline__ void cpwait0() { asm volatile("cp.async.wait_group 0;" ::: "memory"); }

// SMEM layout (byte offsets from dynamic base):
#define OFF_ACTP_HI 0
#define OFF_ACTP_LO 32768
#define OFF_ACTQ_HI 65536
#define OFF_ACTQ_LO 81920
#define OFF_A0(b)   (98304  + (b)*32768)   // hi at +0, lo at +16384
#define OFF_B(b)    (163840 + (b)*32768)
#define SMEM_BYTES  229376

// stage B weights chunk: [128 n x 64 k] hi+lo, swizzled, via cp.async
__device__ __forceinline__ void prefetch_B(uint32_t bufU,
        const __nv_bfloat16* __restrict__ wh, const __nv_bfloat16* __restrict__ wl,
        int kb, int KDIM, int tid) {
#pragma unroll
    for (int it = 0; it < 4; ++it) {
        int i = tid + it * NTHREADS;
        int g = i & 7, n = (i >> 3) & 127, hl = i >> 10;
        const __nv_bfloat16* src = (hl ? wl : wh) + n * KDIM + kb + g * 8;
        uint32_t dst = bufU + hl * 16384 + n * 128 + ((g ^ (n & 7)) << 4);
        cpasync16(dst, src, true);
    }
}

// stage0 A chunk: rows R<128 map to window pairs, from pre-split k
__device__ __forceinline__ void prefetch_A0(uint32_t bufU,
        const __nv_bfloat16* __restrict__ khB, const __nv_bfloat16* __restrict__ klB,
        int kb, int nw, int tid) {
    const int bsel = kb >> 7, d0 = kb & 127;
#pragma unroll
    for (int it = 0; it < 4; ++it) {
        int i = tid + it * NTHREADS;
        int g = i & 7, R = (i >> 3) & 127, hl = i >> 10;
        bool valid = R < 16 * nw;
        int srow = ((R >> 4) << 4) + 2 * (R & 15) + bsel;
        const __nv_bfloat16* base = hl ? klB : khB;
        const __nv_bfloat16* src = base + (size_t)(valid ? srow : 0) * DIMD + d0 + g * 8;
        uint32_t dst = bufU + hl * 16384 + R * 128 + ((g ^ (R & 7)) << 4);
        cpasync16(dst, src, valid);
    }
}

// ---------------------------------------------------------------------------
// One GEMM stage. 16-warp grid: NWR warps in row dim, 16/NWR in col dim.
// Warp computes R row-tiles x T n-tiles (T * (16/NWR) == 16).
// Pipeline order per chunk c:  wait(c) -> barrier -> issue prefetch(c+1) ->
// compute(c).  The barrier proves all warps finished reading buffer
// (c+1)&1 (used by chunk c-1) BEFORE the prefetch overwrites it.
// ---------------------------------------------------------------------------
template<int AMODE, int OUTMODE, int R, int T, int NWR>
__device__ __forceinline__ void run_stage(
    int Ms, int KDIM, int nw,
    const __nv_bfloat16* __restrict__ wh, const __nv_bfloat16* __restrict__ wl,
    const __nv_bfloat16* __restrict__ khB, const __nv_bfloat16* __restrict__ klB,
    uint32_t sb,
    uint32_t aHiU, uint32_t aLoU,      // act source (AMODE 1/2)
    char* outHi, char* outLo,          // act dest (OUTMODE 0)
    float* gout)                        // gmem dest (OUTMODE 1)
{
    const int tid  = threadIdx.x;
    const int lane = tid & 31;
    const int wid  = tid >> 5;
    const int rBeg  = (wid % NWR) * R;
    const int ntBeg = (wid / NWR) * T;

    float acc[R][T][4];
#pragma unroll
    for (int i = 0; i < R; i++)
#pragma unroll
        for (int t = 0; t < T; t++)
#pragma unroll
            for (int j = 0; j < 4; j++) acc[i][t][j] = 0.f;

    const int a_mat    = lane >> 3;
    const int a_rowoff = (lane & 7) + ((a_mat & 1) << 3);
    const int a_koff   = (a_mat >> 1) << 3;
    const int b_nl     = lane & 7;
    const int b_km     = (lane >> 3) << 3;

    const int NC = KDIM / 64;

    // prologue prefetch of chunk 0
    prefetch_B(sb + OFF_B(0), wh, wl, 0, KDIM, tid);
    if (AMODE == 0) prefetch_A0(sb + OFF_A0(0), khB, klB, 0, nw, tid);
    cpcommit();

    for (int c = 0; c < NC; ++c) {
        cpwait0();         // chunk c data landed (this thread's copies)
        __syncthreads();   // all warps: chunk c visible AND done reading buf (c+1)&1

        if (c + 1 < NC) {  // safe now: nobody reads buf (c+1)&1 until next barrier
            int b = (c + 1) & 1;
            prefetch_B(sb + OFF_B(b), wh, wl, (c + 1) * 64, KDIM, tid);
            if (AMODE == 0) prefetch_A0(sb + OFF_A0(b), khB, klB, (c + 1) * 64, nw, tid);
            cpcommit();
        }

        const int kb = c * 64;
        const int bi = c & 1;
        const uint32_t bHiU = sb + OFF_B(bi);
        const uint32_t bLoU = bHiU + 16384;
        uint32_t srcHi, srcLo;
        if (AMODE == 0) { srcHi = sb + OFF_A0(bi); srcLo = srcHi + 16384; }
        else            { srcHi = aHiU;            srcLo = aLoU; }

#pragma unroll
        for (int kq = 0; kq < 64; kq += 32) {
            uint32_t aH[R][8], aL[R][8];
#pragma unroll
            for (int i = 0; i < R; i++) {
                const int Rr = (rBeg + i) * 16 + a_rowoff;
                int offs0, offs1;
                if (AMODE == 0) {
                    int kc0 = kq + a_koff;
                    offs0 = Rr * 128 + (((kc0 >> 3) ^ (Rr & 7)) << 4);
                    int kc1 = kc0 + 16;
                    offs1 = Rr * 128 + (((kc1 >> 3) ^ (Rr & 7)) << 4);
                } else if (AMODE == 1) {
                    int k0 = kb + kq + a_koff;
                    int pr0 = 2 * Rr + (k0 >> 7);
                    int ch0 = (k0 & 127) >> 3;
                    int cs0 = (ch0 & 8) | ((ch0 & 7) ^ ((pr0 >> 1) & 7));
                    offs0 = pr0 * 256 + (cs0 << 4);
                    int k1 = k0 + 16;
                    int pr1 = 2 * Rr + (k1 >> 7);
                    int ch1 = (k1 & 127) >> 3;
                    int cs1 = (ch1 & 8) | ((ch1 & 7) ^ ((pr1 >> 1) & 7));
                    offs1 = pr1 * 256 + (cs1 << 4);
                } else {
                    int k0 = kb + kq + a_koff;
                    int ch0 = k0 >> 3;
                    int cs0 = (ch0 & 8) | ((ch0 & 7) ^ ((Rr >> 1) & 7));
                    offs0 = Rr * 256 + (cs0 << 4);
                    int k1 = k0 + 16;
                    int ch1 = k1 >> 3;
                    int cs1 = (ch1 & 8) | ((ch1 & 7) ^ ((Rr >> 1) & 7));
                    offs1 = Rr * 256 + (cs1 << 4);
                }
                ldmx4(aH[i] + 0, srcHi + offs0);
                ldmx4(aH[i] + 4, srcHi + offs1);
                ldmx4(aL[i] + 0, srcLo + offs0);
                ldmx4(aL[i] + 4, srcLo + offs1);
            }
#pragma unroll
            for (int t = 0; t < T; t++) {
                const int nt = ntBeg + t;
                const int n = (nt << 3) + b_nl;
                const int cs = ((kq + b_km) >> 3) ^ (n & 7);
                const uint32_t boff = n * 128 + (cs << 4);
                uint32_t bH[4], bL[4];
                ldmx4(bH, bHiU + boff);
                ldmx4(bL, bLoU + boff);
#pragma unroll
                for (int i = 0; i < R; i++) {
                    float* cc = acc[i][t];
                    mma16816(cc, aH[i] + 0, bH[0], bH[1]);
                    mma16816(cc, aL[i] + 0, bH[0], bH[1]);
                    mma16816(cc, aH[i] + 0, bL[0], bL[1]);
                    mma16816(cc, aH[i] + 4, bH[2], bH[3]);
                    mma16816(cc, aL[i] + 4, bH[2], bH[3]);
                    mma16816(cc, aH[i] + 4, bL[2], bL[3]);
                }
            }
        }
    }
    __syncthreads();   // all compute done: B/A0 safe for next stage's prologue

    // epilogue
    const int r0  = lane >> 2;
    const int cof = (lane & 3) << 1;
#pragma unroll
    for (int i = 0; i < R; i++) {
#pragma unroll
        for (int t = 0; t < T; t++) {
            const int nt = ntBeg + t;
            const int col = (nt << 3) + cof;
            float* cc = acc[i][t];
#pragma unroll
            for (int h = 0; h < 2; h++) {
                const int r = (rBeg + i) * 16 + r0 + (h << 3);
                if (r < Ms) {
                    float v0 = cc[2*h], v1 = cc[2*h + 1];
                    if (AMODE == 0) {   // stage-0 pe bias, fp32
                        float2 bb = *(const float2*)(g_pew + (r & 15) * 128 + col);
                        v0 += bb.x; v1 += bb.y;
                    }
                    if (OUTMODE == 0) {
                        v0 = silu_f(v0); v1 = silu_f(v1);
                        U2b hi, lo;
                        hi.b[0] = __float2bfloat16(v0);
                        hi.b[1] = __float2bfloat16(v1);
                        lo.b[0] = __float2bfloat16(v0 - __bfloat162float(hi.b[0]));
                        lo.b[1] = __float2bfloat16(v1 - __bfloat162float(hi.b[1]));
                        int cs = (nt & 8) | ((nt & 7) ^ ((r >> 1) & 7));
                        int off = r * 256 + (cs << 4) + ((col & 7) << 1);
                        *(uint32_t*)(outHi + off) = hi.u;
                        *(uint32_t*)(outLo + off) = lo.u;
                    } else {
                        gout[(size_t)r * DIMD + col]     = v0;
                        gout[(size_t)r * DIMD + col + 1] = v1;
                    }
                }
            }
        }
    }
}

__global__ void __launch_bounds__(NTHREADS, 1)
compressor_mma_kernel(float* __restrict__ out)
{
    extern __shared__ char sm[];
    const uint32_t sb = u32p(sm);
    char* actPhi = sm + OFF_ACTP_HI;
    char* actPlo = sm + OFF_ACTP_LO;
    char* actQhi = sm + OFF_ACTQ_HI;
    char* actQlo = sm + OFF_ACTQ_LO;
    const uint32_t uPhi = sb + OFF_ACTP_HI, uPlo = sb + OFF_ACTP_LO;
    const uint32_t uQhi = sb + OFF_ACTQ_HI, uQlo = sb + OFF_ACTQ_LO;

    const int bh    = blockIdx.y;
    const int g     = blockIdx.x;
    const int wbase = g * WPC;
    const int nw    = min(WPC, NB - wbase);
    const int tid   = threadIdx.x;

    if (g == 0 && tid < DIMD)
        out[(size_t)bh * 512 * DIMD + tid] = 0.f;

    const __nv_bfloat16* khB = g_k_hi + ((size_t)bh * S_LEN + (size_t)STRIDE * wbase) * DIMD;
    const __nv_bfloat16* klB = g_k_lo + ((size_t)bh * S_LEN + (size_t)STRIDE * wbase) * DIMD;
    float* gout = out + ((size_t)bh * 512 + 1 + wbase) * DIMD;

    const __nv_bfloat16* wh = g_w_hi;
    const __nv_bfloat16* wl = g_w_lo;

    // 16-warp tilings: <AMODE,OUTMODE,R,T,NWR>
    run_stage<0,0,2,4,4>(16*nw, 256, nw, wh,        wl,        khB, klB, sb, 0, 0,
                         actPhi, actPlo, nullptr);
    run_stage<1,0,1,4,4>(8*nw,  256, nw, wh+32768,  wl+32768,  nullptr, nullptr, sb,
                         uPhi, uPlo, actQhi, actQlo, nullptr);
    run_stage<1,0,1,2,2>(4*nw,  256, nw, wh+65536,  wl+65536,  nullptr, nullptr, sb,
                         uQhi, uQlo, actPhi, actPlo, nullptr);
    run_stage<1,0,1,1,1>(2*nw,  256, nw, wh+98304,  wl+98304,  nullptr, nullptr, sb,
                         uPhi, uPlo, actQhi, actQlo, nullptr);
    run_stage<1,0,1,1,1>(nw,    256, nw, wh+131072, wl+131072, nullptr, nullptr, sb,
                         uQhi, uQlo, actPhi, actPlo, nullptr);
    run_stage<2,1,1,1,1>(nw,    128, nw, wh+163840, wl+163840, nullptr, nullptr, sb,
                         uPhi, uPlo, nullptr, nullptr, gout);
}

extern "C" void kernel_launch(void* const* d_in, const int* in_sizes, int n_in,
                              void* d_out, int out_size)
{
    const float* k  = (const float*)d_in[0];
    const float* pe = (const float*)d_in[1];
    const float* wd = (const float*)d_in[2];
    const float* ws = (const float*)d_in[3];
    float* out = (float*)d_out;

    split_weights_kernel<<<(WTOT + 255) / 256, 256>>>(wd, ws);
    split_k_kernel<<<(int)(KTOT / (256 * 8)), 256>>>(k);
    prep_pew_kernel<<<8, 256>>>(wd, pe);

    cudaFuncSetAttribute(compressor_mma_kernel,
                         cudaFuncAttributeMaxDynamicSharedMemorySize, SMEM_BYTES);
    dim3 grid((NB + WPC - 1) / WPC, BH);  // 64 x 32
    compressor_mma_kernel<<<grid, NTHREADS, SMEM_BYTES>>>(out);
}

// round 6
// speedup vs baseline: 7.3001x; 1.1293x over previous
#include <cuda_runtime.h>
#include <cuda_bf16.h>
#include <cstdint>

#define DIMD     128
#define STRIDE   16
#define S_LEN    8192
#define NB       511
#define BH       32
#define WPC      8
#define NTHREADS 512
#define WTOT     (5*128*256 + 128*128)
#define NPAIRS   4096

// device scratch
__device__ __nv_bfloat16 g_w_hi[WTOT];
__device__ __nv_bfloat16 g_w_lo[WTOT];
__device__ float         g_pew[16 * 128];
__device__ float         g_y[(size_t)BH * NPAIRS * DIMD];   // 64 MB

union U8b { __nv_bfloat16 b[8]; uint4 v; };
union U4b { __nv_bfloat16 b[4]; unsigned long long u; };
union U2b { __nv_bfloat16 b[2]; uint32_t u; };

__global__ void split_weights_kernel(const float* __restrict__ wd,
                                     const float* __restrict__ ws) {
    int i = blockIdx.x * blockDim.x + threadIdx.x;
    if (i >= WTOT) return;
    float v = (i < 5*128*256) ? wd[i] : ws[i - 5*128*256];
    __nv_bfloat16 h = __float2bfloat16(v);
    g_w_hi[i] = h;
    g_w_lo[i] = __float2bfloat16(v - __bfloat162float(h));
}

// PEW[j][n] = sum_d pe[2j,d]*W0[n,d] + pe[2j+1,d]*W0[n,128+d]
__global__ void prep_pew_kernel(const float* __restrict__ wd,
                                const float* __restrict__ pe) {
    int idx = blockIdx.x * blockDim.x + threadIdx.x;   // 2048 total
    int j = idx >> 7, n = idx & 127;
    float s = 0.f;
    for (int d = 0; d < 128; ++d) {
        s += pe[(2*j)*128 + d]   * wd[n*256 + d];
        s += pe[(2*j+1)*128 + d] * wd[n*256 + 128 + d];
    }
    g_pew[idx] = s;
}

// ---------------------------------------------------------------------------

__device__ __forceinline__ uint32_t u32p(const void* p) {
    return (uint32_t)__cvta_generic_to_shared(p);
}
__device__ __forceinline__ void ldmx4(uint32_t* r, uint32_t addr) {
    asm volatile("ldmatrix.sync.aligned.m8n8.x4.shared.b16 {%0,%1,%2,%3}, [%4];"
                 : "=r"(r[0]), "=r"(r[1]), "=r"(r[2]), "=r"(r[3]) : "r"(addr));
}
__device__ __forceinline__ void mma16816(float* c, const uint32_t* a,
                                         uint32_t b0, uint32_t b1) {
    asm volatile("mma.sync.aligned.m16n8k16.row.col.f32.bf16.bf16.f32 "
                 "{%0,%1,%2,%3}, {%4,%5,%6,%7}, {%8,%9}, {%0,%1,%2,%3};"
                 : "+f"(c[0]), "+f"(c[1]), "+f"(c[2]), "+f"(c[3])
                 : "r"(a[0]), "r"(a[1]), "r"(a[2]), "r"(a[3]), "r"(b0), "r"(b1));
}
__device__ __forceinline__ float silu_f(float x) { return x / (1.f + __expf(-x)); }

__device__ __forceinline__ void cpasync16(uint32_t dst, const void* src) {
    asm volatile("cp.async.cg.shared.global [%0], [%1], 16;"
                 :: "r"(dst), "l"(src));
}
__device__ __forceinline__ void cpcommit() {
    asm volatile("cp.async.commit_group;" ::: "memory");
}
__device__ __forceinline__ void cpwait0() { asm volatile("cp.async.wait_group 0;" ::: "memory"); }

// ===========================================================================
// Y-GEMM: Y[bh][j][:] = W0 · [k_{2j}; k_{2j+1}]   (A = k viewed [4096,256])
// M=128 tile per CTA, N=128, K=256 in 64-col chunks, double buffered.
// ===========================================================================
#define YG_SMEM 131072
// smem: A bufs @0,32768 (hi +0, lo +16384); B bufs @65536,98304 (hi/lo same)

__device__ __forceinline__ void yg_prefB(uint32_t bufU, int kb, int tid) {
#pragma unroll
    for (int it = 0; it < 4; ++it) {
        int i = tid + it * 512;                  // 2048
        int g = i & 7, n = (i >> 3) & 127, hl = i >> 10;
        const __nv_bfloat16* src = (hl ? g_w_lo : g_w_hi) + n * 256 + kb + g * 8;
        uint32_t dst = bufU + hl * 16384 + n * 128 + ((g ^ (n & 7)) << 4);
        cpasync16(dst, src);
    }
}

__global__ void __launch_bounds__(512, 1)
ygemm_kernel(const float* __restrict__ k)
{
    extern __shared__ char sm[];
    const uint32_t sb = u32p(sm);
    const int mt = blockIdx.x, bh = blockIdx.y;
    const int tid = threadIdx.x, lane = tid & 31, wid = tid >> 5;
    const float* Abase = k + (size_t)bh * S_LEN * DIMD + (size_t)mt * 128 * 256;

    const int rBeg  = (wid & 3) * 2;    // NWR=4, R=2
    const int ntBeg = (wid >> 2) * 4;   // T=4

    float acc[2][4][4];
#pragma unroll
    for (int i = 0; i < 2; i++)
#pragma unroll
        for (int t = 0; t < 4; t++)
#pragma unroll
            for (int j = 0; j < 4; j++) acc[i][t][j] = 0.f;

    const int a_mat    = lane >> 3;
    const int a_rowoff = (lane & 7) + ((a_mat & 1) << 3);
    const int a_koff   = (a_mat >> 1) << 3;
    const int b_nl     = lane & 7;
    const int b_km     = (lane >> 3) << 3;

    float4 rA[4];
    // --- prologue: chunk 0 ---
#pragma unroll
    for (int t = 0; t < 4; ++t) {
        int f = tid + t * 512, row = f >> 4, fc = f & 15;
        rA[t] = *(const float4*)(Abase + row * 256 + 4 * fc);
    }
    yg_prefB(sb + 65536, 0, tid); cpcommit();
#pragma unroll
    for (int t = 0; t < 4; ++t) {
        int f = tid + t * 512, row = f >> 4, fc = f & 15;
        float v[4] = {rA[t].x, rA[t].y, rA[t].z, rA[t].w};
        U4b hi, lo;
#pragma unroll
        for (int j = 0; j < 4; j++) {
            hi.b[j] = __float2bfloat16(v[j]);
            lo.b[j] = __float2bfloat16(v[j] - __bfloat162float(hi.b[j]));
        }
        int g = fc >> 1;
        int off = row * 128 + ((g ^ (row & 7)) << 4) + (fc & 1) * 8;
        *(unsigned long long*)(sm + off) = hi.u;
        *(unsigned long long*)(sm + 16384 + off) = lo.u;
    }
    cpwait0(); __syncthreads();

    for (int c = 0; c < 4; ++c) {
        if (c < 3) {   // LDG next A chunk + prefetch next B
#pragma unroll
            for (int t = 0; t < 4; ++t) {
                int f = tid + t * 512, row = f >> 4, fc = f & 15;
                rA[t] = *(const float4*)(Abase + row * 256 + (c + 1) * 64 + 4 * fc);
            }
            yg_prefB(sb + 65536 + ((c + 1) & 1) * 32768, (c + 1) * 64, tid);
            cpcommit();
        }
        // compute chunk c
        {
            const uint32_t aHiU = sb + (c & 1) * 32768, aLoU = aHiU + 16384;
            const uint32_t bHiU = sb + 65536 + (c & 1) * 32768, bLoU = bHiU + 16384;
#pragma unroll
            for (int kq = 0; kq < 64; kq += 32) {
                uint32_t aH[2][8], aL[2][8];
#pragma unroll
                for (int i = 0; i < 2; i++) {
                    int Rr = (rBeg + i) * 16 + a_rowoff;
                    int kc0 = kq + a_koff;
                    int offs0 = Rr * 128 + (((kc0 >> 3) ^ (Rr & 7)) << 4);
                    int kc1 = kc0 + 16;
                    int offs1 = Rr * 128 + (((kc1 >> 3) ^ (Rr & 7)) << 4);
                    ldmx4(aH[i] + 0, aHiU + offs0);
                    ldmx4(aH[i] + 4, aHiU + offs1);
                    ldmx4(aL[i] + 0, aLoU + offs0);
                    ldmx4(aL[i] + 4, aLoU + offs1);
                }
#pragma unroll
                for (int t = 0; t < 4; t++) {
                    int n = ((ntBeg + t) << 3) + b_nl;
                    int cs = ((kq + b_km) >> 3) ^ (n & 7);
                    uint32_t boff = n * 128 + (cs << 4);
                    uint32_t bH[4], bL[4];
                    ldmx4(bH, bHiU + boff);
                    ldmx4(bL, bLoU + boff);
#pragma unroll
                    for (int i = 0; i < 2; i++) {
                        float* cc = acc[i][t];
                        mma16816(cc, aH[i] + 0, bH[0], bH[1]);
                        mma16816(cc, aL[i] + 0, bH[0], bH[1]);
                        mma16816(cc, aH[i] + 0, bL[0], bL[1]);
                        mma16816(cc, aH[i] + 4, bH[2], bH[3]);
                        mma16816(cc, aL[i] + 4, bH[2], bH[3]);
                        mma16816(cc, aH[i] + 4, bL[2], bL[3]);
                    }
                }
            }
        }
        if (c < 3) {   // store next A chunk (safe: buf (c+1)&1 readers done last iter)
#pragma unroll
            for (int t = 0; t < 4; ++t) {
                int f = tid + t * 512, row = f >> 4, fc = f & 15;
                float v[4] = {rA[t].x, rA[t].y, rA[t].z, rA[t].w};
                U4b hi, lo;
#pragma unroll
                for (int j = 0; j < 4; j++) {
                    hi.b[j] = __float2bfloat16(v[j]);
                    lo.b[j] = __float2bfloat16(v[j] - __bfloat162float(hi.b[j]));
                }
                int g = fc >> 1;
                int off = ((c + 1) & 1) * 32768 + row * 128 + ((g ^ (row & 7)) << 4) + (fc & 1) * 8;
                *(unsigned long long*)(sm + off) = hi.u;
                *(unsigned long long*)(sm + 16384 + off) = lo.u;
            }
            cpwait0(); __syncthreads();
        }
    }

    // epilogue: fp32 Y store
    float* yout = g_y + ((size_t)bh * NPAIRS + (size_t)mt * 128) * 128;
    const int r0 = lane >> 2, cof = (lane & 3) << 1;
#pragma unroll
    for (int i = 0; i < 2; i++)
#pragma unroll
        for (int t = 0; t < 4; t++) {
            int col = ((ntBeg + t) << 3) + cof;
            float* cc = acc[i][t];
#pragma unroll
            for (int h = 0; h < 2; h++) {
                int r = (rBeg + i) * 16 + r0 + (h << 3);
                *(float2*)(yout + (size_t)r * 128 + col) =
                    make_float2(cc[2*h], cc[2*h + 1]);
            }
        }
}

// ===========================================================================
// Fused kernel: Y-pass (load Y + PEW, silu, split) + stages 1..5.
// SMEM: actP hi@0 lo@32768 (128r x 256B); actQ hi@65536 lo@81920 (64r x 256B);
//       B bufs @98304 + b*65536 : [hl*32768 + half*16384 + n*128 + swz]
// ===========================================================================
#define OFF_B(b)   (98304 + (b)*65536)
#define SMEM_BYTES 229376

__device__ __forceinline__ void prefetch_B128(uint32_t bufU,
        const __nv_bfloat16* __restrict__ wh, const __nv_bfloat16* __restrict__ wl,
        int KDIM, int kb, int tid) {
#pragma unroll
    for (int it = 0; it < 8; ++it) {
        int i = tid + it * 512;                 // 4096
        int g = i & 15, n = (i >> 4) & 127, hl = i >> 11;
        const __nv_bfloat16* src = (hl ? wl : wh) + n * KDIM + kb + g * 8;
        uint32_t dst = bufU + hl * 32768 + (g >> 3) * 16384 + n * 128
                     + (((g & 7) ^ (n & 7)) << 4);
        cpasync16(dst, src);
    }
}

// AMODE 1: A act paired rows (K=256); AMODE 2: A act direct (K=128)
template<int AMODE, int OUTMODE, int R, int T, int NWR>
__device__ __forceinline__ void run_stage(
    int Ms, int KDIM,
    const __nv_bfloat16* __restrict__ wh, const __nv_bfloat16* __restrict__ wl,
    const __nv_bfloat16* __restrict__ whN, const __nv_bfloat16* __restrict__ wlN,
    int KDIMN,
    uint32_t sb, uint32_t aHiU, uint32_t aLoU,
    char* outHi, char* outLo, float* gout)
{
    const int tid  = threadIdx.x;
    const int lane = tid & 31;
    const int wid  = tid >> 5;
    const int rBeg  = (wid % NWR) * R;
    const int ntBeg = (wid / NWR) * T;

    float acc[R][T][4];
#pragma unroll
    for (int i = 0; i < R; i++)
#pragma unroll
        for (int t = 0; t < T; t++)
#pragma unroll
            for (int j = 0; j < 4; j++) acc[i][t][j] = 0.f;

    const int a_mat    = lane >> 3;
    const int a_rowoff = (lane & 7) + ((a_mat & 1) << 3);
    const int a_koff   = (a_mat >> 1) << 3;
    const int b_nl     = lane & 7;
    const int b_km     = (lane >> 3) << 3;

    const int NC = KDIM / 128;

    for (int c = 0; c < NC; ++c) {
        cpwait0();         // chunk c B landed
        __syncthreads();   // visible to all; prior readers of target bufs done

        if (c + 1 < NC) {
            prefetch_B128(sb + OFF_B((c + 1) & 1), wh, wl, KDIM, (c + 1) * 128, tid);
            cpcommit();
        } else if (whN) {  // cross-stage: next stage's chunk 0 -> B(0)
            prefetch_B128(sb + OFF_B(0), whN, wlN, KDIMN, 0, tid);
            cpcommit();
        }

        const int kb = c * 128;
        const uint32_t bHiU = sb + OFF_B(c & 1);
        const uint32_t bLoU = bHiU + 32768;

#pragma unroll
        for (int kq = 0; kq < 128; kq += 32) {
            uint32_t aH[R][8], aL[R][8];
#pragma unroll
            for (int i = 0; i < R; i++) {
                const int Rr = (rBeg + i) * 16 + a_rowoff;
                int offs0, offs1;
                if (AMODE == 1) {
                    int k0 = kb + kq + a_koff;
                    int pr0 = 2 * Rr + (k0 >> 7);
                    int ch0 = (k0 & 127) >> 3;
                    int cs0 = (ch0 & 8) | ((ch0 & 7) ^ ((pr0 >> 1) & 7));
                    offs0 = pr0 * 256 + (cs0 << 4);
                    int k1 = k0 + 16;
                    int pr1 = 2 * Rr + (k1 >> 7);
                    int ch1 = (k1 & 127) >> 3;
                    int cs1 = (ch1 & 8) | ((ch1 & 7) ^ ((pr1 >> 1) & 7));
                    offs1 = pr1 * 256 + (cs1 << 4);
                } else {
                    int k0 = kb + kq + a_koff;
                    int ch0 = k0 >> 3;
                    int cs0 = (ch0 & 8) | ((ch0 & 7) ^ ((Rr >> 1) & 7));
                    offs0 = Rr * 256 + (cs0 << 4);
                    int k1 = k0 + 16;
                    int ch1 = k1 >> 3;
                    int cs1 = (ch1 & 8) | ((ch1 & 7) ^ ((Rr >> 1) & 7));
                    offs1 = Rr * 256 + (cs1 << 4);
                }
                ldmx4(aH[i] + 0, aHiU + offs0);
                ldmx4(aH[i] + 4, aHiU + offs1);
                ldmx4(aL[i] + 0, aLoU + offs0);
                ldmx4(aL[i] + 4, aLoU + offs1);
            }
#pragma unroll
            for (int t = 0; t < T; t++) {
                const int nt = ntBeg + t;
                const int n = (nt << 3) + b_nl;
                const int kcm = kq + b_km;
                const int gg = kcm >> 3;
                const uint32_t boff = (uint32_t)((gg >> 3) * 16384 + n * 128
                                   + (((gg & 7) ^ (n & 7)) << 4));
                uint32_t bH[4], bL[4];
                ldmx4(bH, bHiU + boff);
                ldmx4(bL, bLoU + boff);
#pragma unroll
                for (int i = 0; i < R; i++) {
                    float* cc = acc[i][t];
                    mma16816(cc, aH[i] + 0, bH[0], bH[1]);
                    mma16816(cc, aL[i] + 0, bH[0], bH[1]);
                    mma16816(cc, aH[i] + 0, bL[0], bL[1]);
                    mma16816(cc, aH[i] + 4, bH[2], bH[3]);
                    mma16816(cc, aL[i] + 4, bH[2], bH[3]);
                    mma16816(cc, aH[i] + 4, bL[2], bL[3]);
                }
            }
        }
    }

    // epilogue (no barrier needed: writes target out-buffer only; ordered for
    // next stage by its chunk-0 top barrier)
    const int r0  = lane >> 2;
    const int cof = (lane & 3) << 1;
#pragma unroll
    for (int i = 0; i < R; i++)
#pragma unroll
        for (int t = 0; t < T; t++) {
            const int nt = ntBeg + t;
            const int col = (nt << 3) + cof;
            float* cc = acc[i][t];
#pragma unroll
            for (int h = 0; h < 2; h++) {
                const int r = (rBeg + i) * 16 + r0 + (h << 3);
                if (r < Ms) {
                    float v0 = cc[2*h], v1 = cc[2*h + 1];
                    if (OUTMODE == 0) {
                        v0 = silu_f(v0); v1 = silu_f(v1);
                        U2b hi, lo;
                        hi.b[0] = __float2bfloat16(v0);
                        hi.b[1] = __float2bfloat16(v1);
                        lo.b[0] = __float2bfloat16(v0 - __bfloat162float(hi.b[0]));
                        lo.b[1] = __float2bfloat16(v1 - __bfloat162float(hi.b[1]));
                        int cs = (nt & 8) | ((nt & 7) ^ ((r >> 1) & 7));
                        int off = r * 256 + (cs << 4) + ((col & 7) << 1);
                        *(uint32_t*)(outHi + off) = hi.u;
                        *(uint32_t*)(outLo + off) = lo.u;
                    } else {
                        gout[(size_t)r * DIMD + col]     = v0;
                        gout[(size_t)r * DIMD + col + 1] = v1;
                    }
                }
            }
        }
}

__global__ void __launch_bounds__(NTHREADS, 1)
compressor_mma_kernel(float* __restrict__ out)
{
    extern __shared__ char sm[];
    const uint32_t sb = u32p(sm);
    char* actPhi = sm + 0;
    char* actPlo = sm + 32768;
    char* actQhi = sm + 65536;
    char* actQlo = sm + 81920;
    const uint32_t uPhi = sb + 0,     uPlo = sb + 32768;
    const uint32_t uQhi = sb + 65536, uQlo = sb + 81920;

    const int bh    = blockIdx.y;
    const int g     = blockIdx.x;
    const int wbase = g * WPC;
    const int nw    = min(WPC, NB - wbase);
    const int tid   = threadIdx.x;

    if (g == 0 && tid < DIMD)
        out[(size_t)bh * 512 * DIMD + tid] = 0.f;

    const __nv_bfloat16* wh = g_w_hi;
    const __nv_bfloat16* wl = g_w_lo;

    // prologue: prefetch stage-1 chunk 0 while Y-pass runs
    prefetch_B128(sb + OFF_B(0), wh + 32768, wl + 32768, 256, 0, tid);
    cpcommit();

    // ---- Y-pass: stage-0 output = silu(Y[8*wbase + 8w + r] + PEW[r]) ----
    {
        const int R = tid >> 2, c0 = (tid & 3) * 32;
        if (R < 16 * nw) {
            const float* yrow = g_y + ((size_t)bh * NPAIRS + 8 * wbase
                               + 8 * (R >> 4) + (R & 15)) * 128 + c0;
            const float* prow = g_pew + (R & 15) * 128 + c0;
#pragma unroll
            for (int blk = 0; blk < 4; ++blk) {
                float4 a = *(const float4*)(yrow + blk * 8);
                float4 b = *(const float4*)(yrow + blk * 8 + 4);
                float4 pa = *(const float4*)(prow + blk * 8);
                float4 pb = *(const float4*)(prow + blk * 8 + 4);
                float v[8] = {a.x+pa.x, a.y+pa.y, a.z+pa.z, a.w+pa.w,
                              b.x+pb.x, b.y+pb.y, b.z+pb.z, b.w+pb.w};
                U8b hi, lo;
#pragma unroll
                for (int j = 0; j < 8; j++) {
                    float s = silu_f(v[j]);
                    hi.b[j] = __float2bfloat16(s);
                    lo.b[j] = __float2bfloat16(s - __bfloat162float(hi.b[j]));
                }
                int nt = (c0 >> 3) + blk;
                int cs = (nt & 8) | ((nt & 7) ^ ((R >> 1) & 7));
                *(uint4*)(actPhi + R * 256 + (cs << 4)) = hi.v;
                *(uint4*)(actPlo + R * 256 + (cs << 4)) = lo.v;
            }
        } else {
            uint4 z = make_uint4(0, 0, 0, 0);
#pragma unroll
            for (int blk = 0; blk < 4; ++blk) {
                int nt = (c0 >> 3) + blk;
                int cs = (nt & 8) | ((nt & 7) ^ ((R >> 1) & 7));
                *(uint4*)(actPhi + R * 256 + (cs << 4)) = z;
                *(uint4*)(actPlo + R * 256 + (cs << 4)) = z;
            }
        }
    }
    // (stage-1's chunk-0 top barrier orders Y-pass stores + B arrival)

    float* gout = out + ((size_t)bh * 512 + 1 + wbase) * DIMD;

    // stages 1..5:  in/out ping-pong P->Q->P->Q->P->gmem
    run_stage<1,0,1,4,4>(8*nw, 256, wh+32768,  wl+32768,  wh+65536,  wl+65536,  256,
                         sb, uPhi, uPlo, actQhi, actQlo, nullptr);
    run_stage<1,0,1,2,2>(4*nw, 256, wh+65536,  wl+65536,  wh+98304,  wl+98304,  256,
                         sb, uQhi, uQlo, actPhi, actPlo, nullptr);
    run_stage<1,0,1,1,1>(2*nw, 256, wh+98304,  wl+98304,  wh+131072, wl+131072, 256,
                         sb, uPhi, uPlo, actQhi, actQlo, nullptr);
    run_stage<1,0,1,1,1>(nw,   256, wh+131072, wl+131072, wh+163840, wl+163840, 128,
                         sb, uQhi, uQlo, actPhi, actPlo, nullptr);
    run_stage<2,1,1,1,1>(nw,   128, wh+163840, wl+163840, nullptr,   nullptr,   0,
                         sb, uPhi, uPlo, nullptr, nullptr, gout);
}

extern "C" void kernel_launch(void* const* d_in, const int* in_sizes, int n_in,
                              void* d_out, int out_size)
{
    const float* k  = (const float*)d_in[0];
    const float* pe = (const float*)d_in[1];
    const float* wd = (const float*)d_in[2];
    const float* ws = (const float*)d_in[3];
    float* out = (float*)d_out;

    split_weights_kernel<<<(WTOT + 255) / 256, 256>>>(wd, ws);
    prep_pew_kernel<<<8, 256>>>(wd, pe);

    cudaFuncSetAttribute(ygemm_kernel,
                         cudaFuncAttributeMaxDynamicSharedMemorySize, YG_SMEM);
    ygemm_kernel<<<dim3(NPAIRS / 128, BH), 512, YG_SMEM>>>(k);

    cudaFuncSetAttribute(compressor_mma_kernel,
                         cudaFuncAttributeMaxDynamicSharedMemorySize, SMEM_BYTES);
    compressor_mma_kernel<<<dim3((NB + WPC - 1) / WPC, BH), NTHREADS, SMEM_BYTES>>>(out);
}

// round 7
// speedup vs baseline: 8.9714x; 1.2289x over previous
#include <cuda_runtime.h>
#include <cuda_bf16.h>
#include <cstdint>

#define DIMD   128
#define S_LEN  8192
#define BH     32
#define NWIN   511
#define WTOT   (5*128*256 + 128*128)

#define M1 (BH*NWIN*8)   // 130816
#define M2 (BH*NWIN*4)   // 65408
#define M3 (BH*NWIN*2)   // 32704
#define M4 (BH*NWIN)     // 16352

// device scratch
__device__ __nv_bfloat16 g_w_hi[WTOT];
__device__ __nv_bfloat16 g_w_lo[WTOT];
__device__ float         g_pew[16 * 128];
__device__ __nv_bfloat16 g_a0_hi[(size_t)BH*NWIN*16*128], g_a0_lo[(size_t)BH*NWIN*16*128];
__device__ __nv_bfloat16 g_a1_hi[(size_t)M1*128],         g_a1_lo[(size_t)M1*128];
__device__ __nv_bfloat16 g_a2_hi[(size_t)M2*128],         g_a2_lo[(size_t)M2*128];
__device__ __nv_bfloat16 g_a3_hi[(size_t)M3*128],         g_a3_lo[(size_t)M3*128];
__device__ __nv_bfloat16 g_a4_hi[(size_t)M4*128],         g_a4_lo[(size_t)M4*128];

union U4b { __nv_bfloat16 b[4]; unsigned long long u; };
union U2b { __nv_bfloat16 b[2]; uint32_t u; };

// ---------------------------------------------------------------------------
__global__ void split_weights_kernel(const float* __restrict__ wd,
                                     const float* __restrict__ ws) {
    int i = blockIdx.x * blockDim.x + threadIdx.x;
    if (i >= WTOT) return;
    float v = (i < 5*128*256) ? wd[i] : ws[i - 5*128*256];
    __nv_bfloat16 h = __float2bfloat16(v);
    g_w_hi[i] = h;
    g_w_lo[i] = __float2bfloat16(v - __bfloat162float(h));
}

__global__ void prep_pew_kernel(const float* __restrict__ wd,
                                const float* __restrict__ pe) {
    int idx = blockIdx.x * blockDim.x + threadIdx.x;   // 2048
    int j = idx >> 7, n = idx & 127;
    float s = 0.f;
    for (int d = 0; d < 128; ++d) {
        s += pe[(2*j)*128 + d]   * wd[n*256 + d];
        s += pe[(2*j+1)*128 + d] * wd[n*256 + 128 + d];
    }
    g_pew[idx] = s;
}

__global__ void zero_out_kernel(float* __restrict__ out) {
    int i = blockIdx.x * 256 + threadIdx.x;   // 4096
    if (i < 4096)
        out[(size_t)(i >> 7) * 512 * 128 + (i & 127)] = 0.f;
}

// ---------------------------------------------------------------------------
__device__ __forceinline__ uint32_t u32p(const void* p) {
    return (uint32_t)__cvta_generic_to_shared(p);
}
__device__ __forceinline__ void ldmx4(uint32_t* r, uint32_t addr) {
    asm volatile("ldmatrix.sync.aligned.m8n8.x4.shared.b16 {%0,%1,%2,%3}, [%4];"
                 : "=r"(r[0]), "=r"(r[1]), "=r"(r[2]), "=r"(r[3]) : "r"(addr));
}
__device__ __forceinline__ void mma16816(float* c, const uint32_t* a,
                                         uint32_t b0, uint32_t b1) {
    asm volatile("mma.sync.aligned.m16n8k16.row.col.f32.bf16.bf16.f32 "
                 "{%0,%1,%2,%3}, {%4,%5,%6,%7}, {%8,%9}, {%0,%1,%2,%3};"
                 : "+f"(c[0]), "+f"(c[1]), "+f"(c[2]), "+f"(c[3])
                 : "r"(a[0]), "r"(a[1]), "r"(a[2]), "r"(a[3]), "r"(b0), "r"(b1));
}
__device__ __forceinline__ float silu_f(float x) { return x / (1.f + __expf(-x)); }

__device__ __forceinline__ void cpasync16(uint32_t dst, const void* src) {
    asm volatile("cp.async.cg.shared.global [%0], [%1], 16;" :: "r"(dst), "l"(src));
}
__device__ __forceinline__ void cpasync16z(uint32_t dst, const void* src, bool v) {
    int sz = v ? 16 : 0;
    asm volatile("cp.async.cg.shared.global [%0], [%1], 16, %2;"
                 :: "r"(dst), "l"(src), "r"(sz));
}
__device__ __forceinline__ void cpcommit() {
    asm volatile("cp.async.commit_group;" ::: "memory");
}
__device__ __forceinline__ void cpwait0() { asm volatile("cp.async.wait_group 0;" ::: "memory"); }

__device__ __forceinline__ void silu_split_store(__nv_bfloat16* hiA, __nv_bfloat16* loA,
                                                 size_t idx, float v0, float v1) {
    v0 = silu_f(v0); v1 = silu_f(v1);
    U2b hi, lo;
    hi.b[0] = __float2bfloat16(v0);
    hi.b[1] = __float2bfloat16(v1);
    lo.b[0] = __float2bfloat16(v0 - __bfloat162float(hi.b[0]));
    lo.b[1] = __float2bfloat16(v1 - __bfloat162float(hi.b[1]));
    *(uint32_t*)(hiA + idx) = hi.u;
    *(uint32_t*)(loA + idx) = lo.u;
}

// 64-col K-chunk compute, warp tile R=2 x T=4 (16-warp CTA, 128x128 tile)
__device__ __forceinline__ void mma_chunk64(
    float (&acc)[2][4][4],
    uint32_t aHiU, uint32_t aLoU, uint32_t bHiU, uint32_t bLoU,
    int rBeg, int ntBeg, int lane)
{
    const int a_mat    = lane >> 3;
    const int a_rowoff = (lane & 7) + ((a_mat & 1) << 3);
    const int a_koff   = (a_mat >> 1) << 3;
    const int b_nl     = lane & 7;
    const int b_km     = (lane >> 3) << 3;
#pragma unroll
    for (int kq = 0; kq < 64; kq += 32) {
        uint32_t aH[2][8], aL[2][8];
#pragma unroll
        for (int i = 0; i < 2; i++) {
            int Rr = (rBeg + i) * 16 + a_rowoff;
            int kc0 = kq + a_koff;
            int offs0 = Rr * 128 + (((kc0 >> 3) ^ (Rr & 7)) << 4);
            int offs1 = Rr * 128 + ((((kc0 + 16) >> 3) ^ (Rr & 7)) << 4);
            ldmx4(aH[i] + 0, aHiU + offs0);
            ldmx4(aH[i] + 4, aHiU + offs1);
            ldmx4(aL[i] + 0, aLoU + offs0);
            ldmx4(aL[i] + 4, aLoU + offs1);
        }
#pragma unroll
        for (int t = 0; t < 4; t++) {
            int n = ((ntBeg + t) << 3) + b_nl;
            int cs = ((kq + b_km) >> 3) ^ (n & 7);
            uint32_t boff = n * 128 + (cs << 4);
            uint32_t bH[4], bL[4];
            ldmx4(bH, bHiU + boff);
            ldmx4(bL, bLoU + boff);
#pragma unroll
            for (int i = 0; i < 2; i++) {
                float* cc = acc[i][t];
                mma16816(cc, aH[i] + 0, bH[0], bH[1]);
                mma16816(cc, aL[i] + 0, bH[0], bH[1]);
                mma16816(cc, aH[i] + 0, bL[0], bL[1]);
                mma16816(cc, aH[i] + 4, bH[2], bH[3]);
                mma16816(cc, aL[i] + 4, bH[2], bH[3]);
                mma16816(cc, aH[i] + 4, bL[2], bL[3]);
            }
        }
    }
}

// B chunk [128 n x 64 k] hi+lo -> smem swizzled
__device__ __forceinline__ void gs_prefB(uint32_t bufU,
        const __nv_bfloat16* __restrict__ wh, const __nv_bfloat16* __restrict__ wl,
        int KDIM, int kb, int tid) {
#pragma unroll
    for (int it = 0; it < 4; ++it) {
        int i = tid + it * 512;                  // 2048
        int g = i & 7, n = (i >> 3) & 127, hl = i >> 10;
        const __nv_bfloat16* src = (hl ? wl : wh) + n * KDIM + kb + g * 8;
        uint32_t dst = bufU + hl * 16384 + n * 128 + ((g ^ (n & 7)) << 4);
        cpasync16(dst, src);
    }
}

// A chunk [128 rows x 64 k] hi+lo from pre-split act arrays
__device__ __forceinline__ void gs_prefA(uint32_t bufU,
        const __nv_bfloat16* __restrict__ aHi, const __nv_bfloat16* __restrict__ aLo,
        int KDIM, int Mtot, int mt, int kb, int tid) {
#pragma unroll
    for (int it = 0; it < 4; ++it) {
        int i = tid + it * 512;
        int g = i & 7, row = (i >> 3) & 127, hl = i >> 10;
        int mrow = mt * 128 + row;
        bool v = mrow < Mtot;
        const __nv_bfloat16* src = (hl ? aLo : aHi)
                                 + (size_t)(v ? mrow : 0) * KDIM + kb + g * 8;
        uint32_t dst = bufU + hl * 16384 + row * 128 + ((g ^ (row & 7)) << 4);
        cpasync16z(dst, src, v);
    }
}

// ===========================================================================
// G0: per (mt, bh) compute Y-tile = W0 . pair, epilogue writes stage-0 act
// for BOTH windows sharing each pair (different PEW bias, silu, split).
// smem: A bufs @0,32768 (hi+0, lo+16384); B bufs @65536,98304; pew @131072
// ===========================================================================
#define G0_SMEM (131072 + 8192)

__global__ void __launch_bounds__(512, 1)
g0_kernel(const float* __restrict__ k)
{
    extern __shared__ char sm[];
    const uint32_t sb = u32p(sm);
    float* pews = (float*)(sm + 131072);
    const int mt = blockIdx.x, bh = blockIdx.y;
    const int tid = threadIdx.x, lane = tid & 31, wid = tid >> 5;
    const float* Abase = k + (size_t)bh * S_LEN * DIMD + (size_t)mt * 128 * 256;

    const int rBeg  = (wid & 3) * 2;
    const int ntBeg = (wid >> 2) * 4;

    float acc[2][4][4];
#pragma unroll
    for (int i = 0; i < 2; i++)
#pragma unroll
        for (int t = 0; t < 4; t++)
#pragma unroll
            for (int j = 0; j < 4; j++) acc[i][t][j] = 0.f;

    // pe-bias table to smem (ordered by first mainloop barrier)
    ((float4*)pews)[tid] = ((const float4*)g_pew)[tid];

    float4 rA[4];
    // prologue: A chunk 0 (LDG+split+STS) and B chunk 0 (cp.async)
#pragma unroll
    for (int t = 0; t < 4; ++t) {
        int f = tid + t * 512, row = f >> 4, fc = f & 15;
        rA[t] = *(const float4*)(Abase + row * 256 + 4 * fc);
    }
    gs_prefB(sb + 65536, g_w_hi, g_w_lo, 256, 0, tid); cpcommit();
#pragma unroll
    for (int t = 0; t < 4; ++t) {
        int f = tid + t * 512, row = f >> 4, fc = f & 15;
        float v[4] = {rA[t].x, rA[t].y, rA[t].z, rA[t].w};
        U4b hi, lo;
#pragma unroll
        for (int j = 0; j < 4; j++) {
            hi.b[j] = __float2bfloat16(v[j]);
            lo.b[j] = __float2bfloat16(v[j] - __bfloat162float(hi.b[j]));
        }
        int g = fc >> 1;
        int off = row * 128 + ((g ^ (row & 7)) << 4) + (fc & 1) * 8;
        *(unsigned long long*)(sm + off) = hi.u;
        *(unsigned long long*)(sm + 16384 + off) = lo.u;
    }
    cpwait0(); __syncthreads();

    for (int c = 0; c < 4; ++c) {
        if (c < 3) {
#pragma unroll
            for (int t = 0; t < 4; ++t) {
                int f = tid + t * 512, row = f >> 4, fc = f & 15;
                rA[t] = *(const float4*)(Abase + row * 256 + (c + 1) * 64 + 4 * fc);
            }
            gs_prefB(sb + 65536 + ((c + 1) & 1) * 32768, g_w_hi, g_w_lo, 256,
                     (c + 1) * 64, tid);
            cpcommit();
        }
        mma_chunk64(acc, sb + (c & 1) * 32768, sb + (c & 1) * 32768 + 16384,
                    sb + 65536 + (c & 1) * 32768, sb + 65536 + (c & 1) * 32768 + 16384,
                    rBeg, ntBeg, lane);
        if (c < 3) {
#pragma unroll
            for (int t = 0; t < 4; ++t) {
                int f = tid + t * 512, row = f >> 4, fc = f & 15;
                float v[4] = {rA[t].x, rA[t].y, rA[t].z, rA[t].w};
                U4b hi, lo;
#pragma unroll
                for (int j = 0; j < 4; j++) {
                    hi.b[j] = __float2bfloat16(v[j]);
                    lo.b[j] = __float2bfloat16(v[j] - __bfloat162float(hi.b[j]));
                }
                int g = fc >> 1;
                int off = ((c + 1) & 1) * 32768 + row * 128
                        + ((g ^ (row & 7)) << 4) + (fc & 1) * 8;
                *(unsigned long long*)(sm + off) = hi.u;
                *(unsigned long long*)(sm + 16384 + off) = lo.u;
            }
            cpwait0(); __syncthreads();
        }
    }

    // epilogue: each pair j feeds two act0 rows
    const int r0 = lane >> 2, cof = (lane & 3) << 1;
    const size_t bhbase = (size_t)bh * NWIN;
#pragma unroll
    for (int i = 0; i < 2; i++)
#pragma unroll
        for (int t = 0; t < 4; t++) {
            int col = ((ntBeg + t) << 3) + cof;
            float* cc = acc[i][t];
#pragma unroll
            for (int h = 0; h < 2; h++) {
                int r = (rBeg + i) * 16 + r0 + (h << 3);
                int j = mt * 128 + r;
                float y0 = cc[2*h], y1 = cc[2*h + 1];
                int w1 = j >> 3, ra = j & 7;
                if (w1 < NWIN) {
                    float b0 = pews[ra * 128 + col], b1 = pews[ra * 128 + col + 1];
                    silu_split_store(g_a0_hi, g_a0_lo,
                        ((bhbase + w1) * 16 + ra) * 128 + col, y0 + b0, y1 + b1);
                }
                if (w1 >= 1) {
                    int rb = ra + 8;
                    float b0 = pews[rb * 128 + col], b1 = pews[rb * 128 + col + 1];
                    silu_split_store(g_a0_hi, g_a0_lo,
                        ((bhbase + (w1 - 1)) * 16 + rb) * 128 + col, y0 + b0, y1 + b1);
                }
            }
        }
}

// ===========================================================================
// G1..G5: flat GEMM stages.  smem: A bufs @0,32768; B bufs @65536,98304.
// ===========================================================================
#define GS_SMEM 131072

template<int STAGE>
__global__ void __launch_bounds__(512, 1)
gstage_kernel(float* __restrict__ gout)
{
    constexpr int KDIM = (STAGE == 5) ? 128 : 256;
    constexpr int NC = KDIM / 64;
    const __nv_bfloat16 *aHi, *aLo, *wh, *wl;
    __nv_bfloat16 *oHi = nullptr, *oLo = nullptr;
    int Mtot;
    if constexpr (STAGE == 1) { aHi=g_a0_hi; aLo=g_a0_lo; wh=g_w_hi+32768;  wl=g_w_lo+32768;  oHi=g_a1_hi; oLo=g_a1_lo; Mtot=M1; }
    if constexpr (STAGE == 2) { aHi=g_a1_hi; aLo=g_a1_lo; wh=g_w_hi+65536;  wl=g_w_lo+65536;  oHi=g_a2_hi; oLo=g_a2_lo; Mtot=M2; }
    if constexpr (STAGE == 3) { aHi=g_a2_hi; aLo=g_a2_lo; wh=g_w_hi+98304;  wl=g_w_lo+98304;  oHi=g_a3_hi; oLo=g_a3_lo; Mtot=M3; }
    if constexpr (STAGE == 4) { aHi=g_a3_hi; aLo=g_a3_lo; wh=g_w_hi+131072; wl=g_w_lo+131072; oHi=g_a4_hi; oLo=g_a4_lo; Mtot=M4; }
    if constexpr (STAGE == 5) { aHi=g_a4_hi; aLo=g_a4_lo; wh=g_w_hi+163840; wl=g_w_lo+163840; Mtot=M4; }

    extern __shared__ char sm[];
    const uint32_t sb = u32p(sm);
    const int mt = blockIdx.x;
    const int tid = threadIdx.x, lane = tid & 31, wid = tid >> 5;
    const int rBeg  = (wid & 3) * 2;
    const int ntBeg = (wid >> 2) * 4;

    float acc[2][4][4];
#pragma unroll
    for (int i = 0; i < 2; i++)
#pragma unroll
        for (int t = 0; t < 4; t++)
#pragma unroll
            for (int j = 0; j < 4; j++) acc[i][t][j] = 0.f;

    gs_prefA(sb, aHi, aLo, KDIM, Mtot, mt, 0, tid);
    gs_prefB(sb + 65536, wh, wl, KDIM, 0, tid);
    cpcommit();

    for (int c = 0; c < NC; ++c) {
        cpwait0();
        __syncthreads();
        if (c + 1 < NC) {
            int b = (c + 1) & 1;
            gs_prefA(sb + b * 32768, aHi, aLo, KDIM, Mtot, mt, (c + 1) * 64, tid);
            gs_prefB(sb + 65536 + b * 32768, wh, wl, KDIM, (c + 1) * 64, tid);
            cpcommit();
        }
        mma_chunk64(acc, sb + (c & 1) * 32768, sb + (c & 1) * 32768 + 16384,
                    sb + 65536 + (c & 1) * 32768, sb + 65536 + (c & 1) * 32768 + 16384,
                    rBeg, ntBeg, lane);
    }

    const int r0 = lane >> 2, cof = (lane & 3) << 1;
#pragma unroll
    for (int i = 0; i < 2; i++)
#pragma unroll
        for (int t = 0; t < 4; t++) {
            int col = ((ntBeg + t) << 3) + cof;
            float* cc = acc[i][t];
#pragma unroll
            for (int h = 0; h < 2; h++) {
                int r = (rBeg + i) * 16 + r0 + (h << 3);
                int m = mt * 128 + r;
                if (m < Mtot) {
                    if constexpr (STAGE < 5) {
                        silu_split_store(oHi, oLo, (size_t)m * 128 + col,
                                         cc[2*h], cc[2*h + 1]);
                    } else {
                        int bh = m / NWIN, w = m % NWIN;
                        *(float2*)(gout + ((size_t)bh * 512 + 1 + w) * 128 + col) =
                            make_float2(cc[2*h], cc[2*h + 1]);
                    }
                }
            }
        }
}

extern "C" void kernel_launch(void* const* d_in, const int* in_sizes, int n_in,
                              void* d_out, int out_size)
{
    const float* k  = (const float*)d_in[0];
    const float* pe = (const float*)d_in[1];
    const float* wd = (const float*)d_in[2];
    const float* ws = (const float*)d_in[3];
    float* out = (float*)d_out;

    split_weights_kernel<<<(WTOT + 255) / 256, 256>>>(wd, ws);
    prep_pew_kernel<<<8, 256>>>(wd, pe);
    zero_out_kernel<<<16, 256>>>(out);

    cudaFuncSetAttribute(g0_kernel,
                         cudaFuncAttributeMaxDynamicSharedMemorySize, G0_SMEM);
    cudaFuncSetAttribute(gstage_kernel<1>,
                         cudaFuncAttributeMaxDynamicSharedMemorySize, GS_SMEM);
    cudaFuncSetAttribute(gstage_kernel<2>,
                         cudaFuncAttributeMaxDynamicSharedMemorySize, GS_SMEM);
    cudaFuncSetAttribute(gstage_kernel<3>,
                         cudaFuncAttributeMaxDynamicSharedMemorySize, GS_SMEM);
    cudaFuncSetAttribute(gstage_kernel<4>,
                         cudaFuncAttributeMaxDynamicSharedMemorySize, GS_SMEM);
    cudaFuncSetAttribute(gstage_kernel<5>,
                         cudaFuncAttributeMaxDynamicSharedMemorySize, GS_SMEM);

    g0_kernel<<<dim3(32, BH), 512, G0_SMEM>>>(k);
    gstage_kernel<1><<<(M1 + 127) / 128, 512, GS_SMEM>>>(out);   // 1022
    gstage_kernel<2><<<(M2 + 127) / 128, 512, GS_SMEM>>>(out);   // 511
    gstage_kernel<3><<<(M3 + 127) / 128, 512, GS_SMEM>>>(out);   // 256
    gstage_kernel<4><<<(M4 + 127) / 128, 512, GS_SMEM>>>(out);   // 128
    gstage_kernel<5><<<(M4 + 127) / 128, 512, GS_SMEM>>>(out);   // 128
}